// round 5
// baseline (speedup 1.0000x reference)
#include <cuda_runtime.h>
#include <cuda_bf16.h>
#include <math.h>
#include <stdint.h>

// Problem constants (B=2048, A=32, D=128, H=256)
#define NB    2048
#define NA    32
#define NROWS (NB * NA)   // 65536
#define DIN   128
#define HD    256
#define H3    768

// ---------------------------------------------------------------------------
// Scratch (__device__ globals; uint4 arrays guarantee 16B alignment)
// ---------------------------------------------------------------------------
__device__ float g_h [(size_t)NROWS * HD];
__device__ float g_h1[(size_t)NROWS * HD];
__device__ float g_gh[(size_t)NROWS * H3];
__device__ float g_gi[(size_t)NROWS * H3];

__device__ uint4 g_obs_hi[(size_t)NROWS * DIN / 8];
__device__ uint4 g_obs_lo[(size_t)NROWS * DIN / 8];
__device__ uint4 g_e_hi  [(size_t)NROWS * HD / 8];   // e, later reused as comm c
__device__ uint4 g_e_lo  [(size_t)NROWS * HD / 8];
__device__ uint4 g_hh_hi [(size_t)NROWS * HD / 8];   // h split
__device__ uint4 g_hh_lo [(size_t)NROWS * HD / 8];
__device__ uint4 g_h1_hi [(size_t)NROWS * HD / 8];
__device__ uint4 g_h1_lo [(size_t)NROWS * HD / 8];
__device__ uint4 g_ew_hi [(size_t)HD * DIN / 8];
__device__ uint4 g_ew_lo [(size_t)HD * DIN / 8];
__device__ uint4 g_fw_hi [(size_t)HD * HD / 8];
__device__ uint4 g_fw_lo [(size_t)HD * HD / 8];
__device__ uint4 g_wih_hi[(size_t)H3 * HD / 8];
__device__ uint4 g_wih_lo[(size_t)H3 * HD / 8];
__device__ uint4 g_whh_hi[(size_t)H3 * HD / 8];
__device__ uint4 g_whh_lo[(size_t)H3 * HD / 8];

__device__ __forceinline__ float sigmoidf_(float x) { return 1.0f / (1.0f + expf(-x)); }

__device__ __forceinline__ uint32_t smem_to_u32(const void* p) {
    uint32_t a;
    asm("{ .reg .u64 t; cvta.to.shared.u64 t, %1; cvt.u32.u64 %0, t; }" : "=r"(a) : "l"(p));
    return a;
}

// 64-byte-row swizzle: fold row bits [8:7] into 16B-chunk bits [5:4]
#define SWZ64(off) ((off) ^ (((off) >> 3) & 0x30))

// ---------------------------------------------------------------------------
// mma / ldmatrix / cp.async primitives (baseline sm_80+ ISA)
// ---------------------------------------------------------------------------
__device__ __forceinline__ void mma_bf16(float* c, uint32_t a0, uint32_t a1, uint32_t a2,
                                         uint32_t a3, uint32_t b0, uint32_t b1) {
    asm volatile(
        "mma.sync.aligned.m16n8k16.row.col.f32.bf16.bf16.f32 "
        "{%0,%1,%2,%3}, {%4,%5,%6,%7}, {%8,%9}, {%0,%1,%2,%3};"
        : "+f"(c[0]), "+f"(c[1]), "+f"(c[2]), "+f"(c[3])
        : "r"(a0), "r"(a1), "r"(a2), "r"(a3), "r"(b0), "r"(b1));
}
__device__ __forceinline__ void ldm_x4(uint32_t* r, uint32_t addr) {
    asm volatile("ldmatrix.sync.aligned.m8n8.x4.shared.b16 {%0,%1,%2,%3}, [%4];"
                 : "=r"(r[0]), "=r"(r[1]), "=r"(r[2]), "=r"(r[3]) : "r"(addr));
}
__device__ __forceinline__ void ldm_x2(uint32_t* r, uint32_t addr) {
    asm volatile("ldmatrix.sync.aligned.m8n8.x2.shared.b16 {%0,%1}, [%2];"
                 : "=r"(r[0]), "=r"(r[1]) : "r"(addr));
}
__device__ __forceinline__ void cp16(uint32_t dst, const void* src) {
    asm volatile("cp.async.cg.shared.global [%0], [%1], 16;" :: "r"(dst), "l"(src));
}
#define CP_COMMIT()  asm volatile("cp.async.commit_group;")
#define CP_WAIT(n)   asm volatile("cp.async.wait_group %0;" :: "n"(n))

// hi/lo bf16 split helpers
__device__ __forceinline__ void split2(float a, float b, uint32_t& hi, uint32_t& lo) {
    __nv_bfloat16 ha = __float2bfloat16_rn(a);
    __nv_bfloat16 hb = __float2bfloat16_rn(b);
    float ra = a - __bfloat162float(ha);
    float rb = b - __bfloat162float(hb);
    __nv_bfloat16 la = __float2bfloat16_rn(ra);
    __nv_bfloat16 lb = __float2bfloat16_rn(rb);
    hi = (uint32_t)__bfloat16_as_ushort(ha) | ((uint32_t)__bfloat16_as_ushort(hb) << 16);
    lo = (uint32_t)__bfloat16_as_ushort(la) | ((uint32_t)__bfloat16_as_ushort(lb) << 16);
}

// ---------------------------------------------------------------------------
// fp32 -> bf16 hi/lo conversion (weights + obs)
// ---------------------------------------------------------------------------
__global__ void convert_split(const float4* __restrict__ src,
                              uint2* __restrict__ hi, uint2* __restrict__ lo, int n4)
{
    const int i = blockIdx.x * blockDim.x + threadIdx.x;
    if (i >= n4) return;
    float4 v = src[i];
    uint2 H, L;
    split2(v.x, v.y, H.x, L.x);
    split2(v.z, v.w, H.y, L.y);
    hi[i] = H;
    lo[i] = L;
}

// ---------------------------------------------------------------------------
// bf16-split GEMM, cp.async double-buffered, wide-N tile:
//   C[N,M] = A[N,K] @ W[M,K]^T + bias  (A, W pre-split into hi/lo bf16)
// CTA tile 128x256, KC=32, 2 stages (96KB smem), 8 warps (2m x 4n), warp 64x64.
// ---------------------------------------------------------------------------
#define ST_AH 0
#define ST_AL 8192
#define ST_WH 16384
#define ST_WL 32768
#define ST_SZ 49152
#define SM_TOTAL (2 * ST_SZ)

template <bool RELU, bool WF32, bool WSPLIT>
__global__ __launch_bounds__(256, 1)
void mma_gemm2(const __nv_bfloat16* __restrict__ Ahg, const __nv_bfloat16* __restrict__ Alg,
               const __nv_bfloat16* __restrict__ Whg, const __nv_bfloat16* __restrict__ Wlg,
               const float* __restrict__ bias, float* __restrict__ C,
               __nv_bfloat16* __restrict__ Ch, __nv_bfloat16* __restrict__ Cl,
               int K, int M)
{
    extern __shared__ char smem[];
    const uint32_t sb = smem_to_u32(smem);
    const int tid  = threadIdx.x;
    const int wid  = tid >> 5;
    const int lane = tid & 31;
    const int row0 = blockIdx.y * 128;
    const int col0 = blockIdx.x * 256;
    const int wm0  = (wid >> 2) * 64;   // 0 or 64
    const int wn0  = (wid & 3) * 64;    // 0,64,128,192

    const int a_row = wm0 + (lane & 15);
    const int a_kb  = ((lane >> 4) & 1) * 16;
    const int b_row = wn0 + (lane & 7);
    const int b_kb  = ((lane >> 3) & 1) * 16;

    // per-thread cp.async mapping: rows split 64B -> 4 x 16B chunks
    // A: 128 rows (2 iters), W: 256 rows (4 iters)
    uint32_t swA[2], swW[4];
    const __nv_bfloat16 *pAh[2], *pAl[2], *pWh[4], *pWl[4];
#pragma unroll
    for (int it = 0; it < 2; it++) {
        int g = tid + it * 256;
        int r = g >> 2, c16 = g & 3;
        swA[it] = SWZ64((uint32_t)(r * 64 + c16 * 16));
        pAh[it] = Ahg + (size_t)(row0 + r) * K + c16 * 8;
        pAl[it] = Alg + (size_t)(row0 + r) * K + c16 * 8;
    }
#pragma unroll
    for (int it = 0; it < 4; it++) {
        int g = tid + it * 256;
        int r = g >> 2, c16 = g & 3;
        swW[it] = SWZ64((uint32_t)(r * 64 + c16 * 16));
        pWh[it] = Whg + (size_t)(col0 + r) * K + c16 * 8;
        pWl[it] = Wlg + (size_t)(col0 + r) * K + c16 * 8;
    }

    float acc[4][8][4];
#pragma unroll
    for (int i = 0; i < 4; i++)
#pragma unroll
        for (int j = 0; j < 8; j++)
#pragma unroll
            for (int q = 0; q < 4; q++) acc[i][j][q] = 0.f;

    const int nch = K >> 5;  // K/32

    // prologue: prefetch chunk 0 into stage 0
#pragma unroll
    for (int it = 0; it < 2; it++) {
        cp16(sb + ST_AH + swA[it], pAh[it]);
        cp16(sb + ST_AL + swA[it], pAl[it]);
    }
#pragma unroll
    for (int it = 0; it < 4; it++) {
        cp16(sb + ST_WH + swW[it], pWh[it]);
        cp16(sb + ST_WL + swW[it], pWl[it]);
    }
    CP_COMMIT();

    for (int ch = 0; ch < nch; ch++) {
        const uint32_t sbase = sb + (uint32_t)(ch & 1) * ST_SZ;
        if (ch + 1 < nch) {
            const uint32_t nbase = sb + (uint32_t)((ch + 1) & 1) * ST_SZ;
            const int koff = (ch + 1) * 32;
#pragma unroll
            for (int it = 0; it < 2; it++) {
                cp16(nbase + ST_AH + swA[it], pAh[it] + koff);
                cp16(nbase + ST_AL + swA[it], pAl[it] + koff);
            }
#pragma unroll
            for (int it = 0; it < 4; it++) {
                cp16(nbase + ST_WH + swW[it], pWh[it] + koff);
                cp16(nbase + ST_WL + swW[it], pWl[it] + koff);
            }
            CP_COMMIT();
            CP_WAIT(1);
        } else {
            CP_WAIT(0);
        }
        __syncthreads();

#pragma unroll
        for (int ks = 0; ks < 2; ks++) {
            uint32_t Ah[4][4], Al[4][4], Bh[8][2], Bl[8][2];
#pragma unroll
            for (int fm = 0; fm < 4; fm++) {
                uint32_t loc = SWZ64((uint32_t)((a_row + fm * 16) * 64 + ks * 32 + a_kb));
                ldm_x4(Ah[fm], sbase + ST_AH + loc);
                ldm_x4(Al[fm], sbase + ST_AL + loc);
            }
#pragma unroll
            for (int fn = 0; fn < 8; fn++) {
                uint32_t loc = SWZ64((uint32_t)((b_row + fn * 8) * 64 + ks * 32 + b_kb));
                ldm_x2(Bh[fn], sbase + ST_WH + loc);
                ldm_x2(Bl[fn], sbase + ST_WL + loc);
            }
#pragma unroll
            for (int fm = 0; fm < 4; fm++)
#pragma unroll
                for (int fn = 0; fn < 8; fn++) {
                    float* c = acc[fm][fn];
                    mma_bf16(c, Ah[fm][0], Ah[fm][1], Ah[fm][2], Ah[fm][3], Bh[fn][0], Bh[fn][1]);
                    mma_bf16(c, Ah[fm][0], Ah[fm][1], Ah[fm][2], Ah[fm][3], Bl[fn][0], Bl[fn][1]);
                    mma_bf16(c, Al[fm][0], Al[fm][1], Al[fm][2], Al[fm][3], Bh[fn][0], Bh[fn][1]);
                }
        }
        __syncthreads();
    }

    // epilogue
    const int gid  = lane >> 2;
    const int tid4 = lane & 3;
#pragma unroll
    for (int fn = 0; fn < 8; fn++) {
        const int col = col0 + wn0 + fn * 8 + 2 * tid4;
        const float b0 = bias[col], b1 = bias[col + 1];
#pragma unroll
        for (int fm = 0; fm < 4; fm++) {
            const int rlo = row0 + wm0 + fm * 16 + gid;
            float2 v0, v1;
            v0.x = acc[fm][fn][0] + b0;  v0.y = acc[fm][fn][1] + b1;
            v1.x = acc[fm][fn][2] + b0;  v1.y = acc[fm][fn][3] + b1;
            if (RELU) {
                v0.x = fmaxf(v0.x, 0.f); v0.y = fmaxf(v0.y, 0.f);
                v1.x = fmaxf(v1.x, 0.f); v1.y = fmaxf(v1.y, 0.f);
            }
            if (WF32) {
                *reinterpret_cast<float2*>(C + (size_t)rlo * M + col)       = v0;
                *reinterpret_cast<float2*>(C + (size_t)(rlo + 8) * M + col) = v1;
            }
            if (WSPLIT) {
                uint32_t h0, l0, h1, l1;
                split2(v0.x, v0.y, h0, l0);
                split2(v1.x, v1.y, h1, l1);
                *reinterpret_cast<uint32_t*>(Ch + (size_t)rlo * M + col)       = h0;
                *reinterpret_cast<uint32_t*>(Cl + (size_t)rlo * M + col)       = l0;
                *reinterpret_cast<uint32_t*>(Ch + (size_t)(rlo + 8) * M + col) = h1;
                *reinterpret_cast<uint32_t*>(Cl + (size_t)(rlo + 8) * M + col) = l1;
            }
        }
    }
}

// ---------------------------------------------------------------------------
// GRU gates k=0 (x==0 -> gi == b_ih): writes h1 fp32 AND h1 hi/lo bf16.
// ---------------------------------------------------------------------------
__global__ void gates0_kernel(const float* __restrict__ gh,
                              const float* __restrict__ b_ih,
                              const float* __restrict__ h,
                              float* __restrict__ h1,
                              uint2* __restrict__ h1_hi, uint2* __restrict__ h1_lo)
{
    const int idx = blockIdx.x * blockDim.x + threadIdx.x;  // over NROWS*64
    const int i = idx >> 6;
    const int q = idx & 63;
    const float4* ghr = reinterpret_cast<const float4*>(gh + (size_t)i * H3);
    const float4* bi  = reinterpret_cast<const float4*>(b_ih);
    float4 gr = ghr[q], gz = ghr[64 + q], gn = ghr[128 + q];
    float4 br = bi[q],  bz = bi[64 + q],  bn = bi[128 + q];
    float4 hh = reinterpret_cast<const float4*>(h)[(size_t)i * 64 + q];
    float4 o;
    { float r = sigmoidf_(br.x + gr.x), z = sigmoidf_(bz.x + gz.x);
      float n = tanhf(bn.x + r * gn.x); o.x = (1.f - z) * n + z * hh.x; }
    { float r = sigmoidf_(br.y + gr.y), z = sigmoidf_(bz.y + gz.y);
      float n = tanhf(bn.y + r * gn.y); o.y = (1.f - z) * n + z * hh.y; }
    { float r = sigmoidf_(br.z + gr.z), z = sigmoidf_(bz.z + gz.z);
      float n = tanhf(bn.z + r * gn.z); o.z = (1.f - z) * n + z * hh.z; }
    { float r = sigmoidf_(br.w + gr.w), z = sigmoidf_(bz.w + gz.w);
      float n = tanhf(bn.w + r * gn.w); o.w = (1.f - z) * n + z * hh.w; }
    reinterpret_cast<float4*>(h1)[(size_t)i * 64 + q] = o;
    uint2 H, L;
    split2(o.x, o.y, H.x, L.x);
    split2(o.z, o.w, H.y, L.y);
    h1_hi[(size_t)i * 64 + q] = H;
    h1_lo[(size_t)i * 64 + q] = L;
}

// ---------------------------------------------------------------------------
// Comm: c[b,a,:] = (sum_a' h1[b,a',:] - h1[b,a,:]) / NA, written as bf16 hi/lo
// ---------------------------------------------------------------------------
__global__ void comm_kernel(const float* __restrict__ h1,
                            __nv_bfloat16* __restrict__ c_hi,
                            __nv_bfloat16* __restrict__ c_lo)
{
    const int b = blockIdx.x;
    const int j = threadIdx.x;
    const float* base = h1 + (size_t)b * NA * HD + j;
    float v[NA];
    float s = 0.f;
#pragma unroll
    for (int a = 0; a < NA; a++) { v[a] = base[a * HD]; s += v[a]; }
    const float inv = 1.f / (float)NA;
    const size_t off = (size_t)b * NA * HD + j;
#pragma unroll
    for (int a = 0; a < NA; a++) {
        float val = (s - v[a]) * inv;
        __nv_bfloat16 hv = __float2bfloat16_rn(val);
        c_hi[off + a * HD] = hv;
        c_lo[off + a * HD] = __float2bfloat16_rn(val - __bfloat162float(hv));
    }
}

// ---------------------------------------------------------------------------
// GRU gates k=1 fused with H->1 decoder. 4 rows / 256-thread block.
// ---------------------------------------------------------------------------
__global__ void gates1_dec_kernel(const float* __restrict__ gi,
                                  const float* __restrict__ gh,
                                  const float* __restrict__ h1,
                                  const float* __restrict__ dec_W,
                                  const float* __restrict__ dec_b,
                                  float* __restrict__ out)
{
    const int tid = threadIdx.x;
    const int i = blockIdx.x * 4 + (tid >> 6);
    const int q = tid & 63;
    const float4* gir = reinterpret_cast<const float4*>(gi + (size_t)i * H3);
    const float4* ghr = reinterpret_cast<const float4*>(gh + (size_t)i * H3);
    float4 ir = gir[q], iz = gir[64 + q], in_ = gir[128 + q];
    float4 hr = ghr[q], hz = ghr[64 + q], hn = ghr[128 + q];
    float4 hp = reinterpret_cast<const float4*>(h1)[(size_t)i * 64 + q];
    float4 dw = reinterpret_cast<const float4*>(dec_W)[q];

    float p = 0.f;
    { float r = sigmoidf_(ir.x + hr.x), z = sigmoidf_(iz.x + hz.x);
      float n = tanhf(in_.x + r * hn.x); p += ((1.f - z) * n + z * hp.x) * dw.x; }
    { float r = sigmoidf_(ir.y + hr.y), z = sigmoidf_(iz.y + hz.y);
      float n = tanhf(in_.y + r * hn.y); p += ((1.f - z) * n + z * hp.y) * dw.y; }
    { float r = sigmoidf_(ir.z + hr.z), z = sigmoidf_(iz.z + hz.z);
      float n = tanhf(in_.z + r * hn.z); p += ((1.f - z) * n + z * hp.z) * dw.z; }
    { float r = sigmoidf_(ir.w + hr.w), z = sigmoidf_(iz.w + hz.w);
      float n = tanhf(in_.w + r * hn.w); p += ((1.f - z) * n + z * hp.w) * dw.w; }
#pragma unroll
    for (int o = 16; o > 0; o >>= 1) p += __shfl_down_sync(0xffffffffu, p, o);
    __shared__ float red[8];
    if ((tid & 31) == 0) red[tid >> 5] = p;
    __syncthreads();
    if (tid < 4) out[blockIdx.x * 4 + tid] = red[2 * tid] + red[2 * tid + 1] + dec_b[0];
}

// ---------------------------------------------------------------------------
// Launch
// ---------------------------------------------------------------------------
extern "C" void kernel_launch(void* const* d_in, const int* in_sizes, int n_in,
                              void* d_out, int out_size)
{
    const float* obs    = (const float*)d_in[0];
    const float* enc_W  = (const float*)d_in[2];
    const float* enc_b  = (const float*)d_in[3];
    const float* fobs_W = (const float*)d_in[4];
    const float* fobs_b = (const float*)d_in[5];
    const float* W_ih   = (const float*)d_in[6];
    const float* b_ih   = (const float*)d_in[7];
    const float* W_hh   = (const float*)d_in[8];
    const float* b_hh   = (const float*)d_in[9];
    const float* dec_W  = (const float*)d_in[10];
    const float* dec_b  = (const float*)d_in[11];
    float* out = (float*)d_out;

    float *h, *h1, *gh, *gi;
    cudaGetSymbolAddress((void**)&h,  g_h);
    cudaGetSymbolAddress((void**)&h1, g_h1);
    cudaGetSymbolAddress((void**)&gh, g_gh);
    cudaGetSymbolAddress((void**)&gi, g_gi);

    void *obs_hi, *obs_lo, *e_hi, *e_lo, *hh_hi, *hh_lo, *h1_hi, *h1_lo;
    void *ew_hi, *ew_lo, *fw_hi, *fw_lo, *wih_hi, *wih_lo, *whh_hi, *whh_lo;
    cudaGetSymbolAddress(&obs_hi, g_obs_hi);  cudaGetSymbolAddress(&obs_lo, g_obs_lo);
    cudaGetSymbolAddress(&e_hi,  g_e_hi);     cudaGetSymbolAddress(&e_lo,  g_e_lo);
    cudaGetSymbolAddress(&hh_hi, g_hh_hi);    cudaGetSymbolAddress(&hh_lo, g_hh_lo);
    cudaGetSymbolAddress(&h1_hi, g_h1_hi);    cudaGetSymbolAddress(&h1_lo, g_h1_lo);
    cudaGetSymbolAddress(&ew_hi, g_ew_hi);    cudaGetSymbolAddress(&ew_lo, g_ew_lo);
    cudaGetSymbolAddress(&fw_hi, g_fw_hi);    cudaGetSymbolAddress(&fw_lo, g_fw_lo);
    cudaGetSymbolAddress(&wih_hi, g_wih_hi);  cudaGetSymbolAddress(&wih_lo, g_wih_lo);
    cudaGetSymbolAddress(&whh_hi, g_whh_hi);  cudaGetSymbolAddress(&whh_lo, g_whh_lo);

    cudaFuncSetAttribute(mma_gemm2<true , false, true >, cudaFuncAttributeMaxDynamicSharedMemorySize, SM_TOTAL);
    cudaFuncSetAttribute(mma_gemm2<false, true , true >, cudaFuncAttributeMaxDynamicSharedMemorySize, SM_TOTAL);
    cudaFuncSetAttribute(mma_gemm2<false, true , false>, cudaFuncAttributeMaxDynamicSharedMemorySize, SM_TOTAL);

    typedef const __nv_bfloat16* bfp;
    typedef __nv_bfloat16* bfpm;

    // 0) pre-split obs + weights to bf16 hi/lo
    convert_split<<<(NROWS * DIN / 4 + 255) / 256, 256>>>((const float4*)obs, (uint2*)obs_hi, (uint2*)obs_lo, NROWS * DIN / 4);
    convert_split<<<(HD * DIN / 4 + 255) / 256, 256>>>((const float4*)enc_W,  (uint2*)ew_hi,  (uint2*)ew_lo,  HD * DIN / 4);
    convert_split<<<(HD * HD  / 4 + 255) / 256, 256>>>((const float4*)fobs_W, (uint2*)fw_hi,  (uint2*)fw_lo,  HD * HD / 4);
    convert_split<<<(H3 * HD  / 4 + 255) / 256, 256>>>((const float4*)W_ih,   (uint2*)wih_hi, (uint2*)wih_lo, H3 * HD / 4);
    convert_split<<<(H3 * HD  / 4 + 255) / 256, 256>>>((const float4*)W_hh,   (uint2*)whh_hi, (uint2*)whh_lo, H3 * HD / 4);

    const dim3 blk(256);
    const int rowBlocks = NROWS / 128;  // 512

    // 1) e = relu(obs @ enc_W^T + enc_b) -> e_hi/e_lo       K=128, M=256
    mma_gemm2<true, false, true><<<dim3(1, rowBlocks), blk, SM_TOTAL>>>(
        (bfp)obs_hi, (bfp)obs_lo, (bfp)ew_hi, (bfp)ew_lo, enc_b,
        nullptr, (bfpm)e_hi, (bfpm)e_lo, DIN, HD);
    // 2) h = e @ fobs_W^T + fobs_b -> h fp32 + h_hi/h_lo    K=256, M=256
    mma_gemm2<false, true, true><<<dim3(1, rowBlocks), blk, SM_TOTAL>>>(
        (bfp)e_hi, (bfp)e_lo, (bfp)fw_hi, (bfp)fw_lo, fobs_b,
        h, (bfpm)hh_hi, (bfpm)hh_lo, HD, HD);
    // 3) gh = h @ W_hh^T + b_hh                             K=256, M=768
    mma_gemm2<false, true, false><<<dim3(3, rowBlocks), blk, SM_TOTAL>>>(
        (bfp)hh_hi, (bfp)hh_lo, (bfp)whh_hi, (bfp)whh_lo, b_hh,
        gh, nullptr, nullptr, HD, H3);
    // 4) GRU k=0 gates -> h1 (fp32 + hi/lo)
    gates0_kernel<<<(NROWS * 64) / 256, 256>>>(gh, b_ih, h, h1, (uint2*)h1_hi, (uint2*)h1_lo);
    // 5) c = masked mean -> c_hi/c_lo (reuse e buffers)
    comm_kernel<<<NB, HD>>>(h1, (bfpm)e_hi, (bfpm)e_lo);
    // 6) gi = c @ W_ih^T + b_ih
    mma_gemm2<false, true, false><<<dim3(3, rowBlocks), blk, SM_TOTAL>>>(
        (bfp)e_hi, (bfp)e_lo, (bfp)wih_hi, (bfp)wih_lo, b_ih,
        gi, nullptr, nullptr, HD, H3);
    // 7) gh = h1 @ W_hh^T + b_hh
    mma_gemm2<false, true, false><<<dim3(3, rowBlocks), blk, SM_TOTAL>>>(
        (bfp)h1_hi, (bfp)h1_lo, (bfp)whh_hi, (bfp)whh_lo, b_hh,
        gh, nullptr, nullptr, HD, H3);
    // 8) GRU k=1 gates + decoder -> out
    gates1_dec_kernel<<<NROWS / 4, 256>>>(gi, gh, h1, dec_W, dec_b, out);
}

// round 6
// speedup vs baseline: 1.0901x; 1.0901x over previous
#include <cuda_runtime.h>
#include <cuda_bf16.h>
#include <math.h>
#include <stdint.h>

// Problem constants (B=2048, A=32, D=128, H=256)
#define NB    2048
#define NA    32
#define NROWS (NB * NA)   // 65536
#define DIN   128
#define HD    256
#define H3    768
#define H6    1536

// ---------------------------------------------------------------------------
// Scratch (__device__ globals; uint4 arrays guarantee 16B alignment)
// ---------------------------------------------------------------------------
__device__ float g_h   [(size_t)NROWS * HD];
__device__ float g_h1  [(size_t)NROWS * HD];
__device__ float g_gh  [(size_t)NROWS * H3];    // k=0 gh
__device__ float g_gcat[(size_t)NROWS * H6];    // k=1: [h1@W_ih | h1@W_hh + b_hh]
__device__ float g_sg  [(size_t)NB * H3];       // S @ W_ih^T
__device__ float g_bias_cat[H6];

__device__ uint4 g_obs_hi[(size_t)NROWS * DIN / 8];
__device__ uint4 g_obs_lo[(size_t)NROWS * DIN / 8];
__device__ uint4 g_e_hi  [(size_t)NROWS * HD / 8];
__device__ uint4 g_e_lo  [(size_t)NROWS * HD / 8];
__device__ uint4 g_hh_hi [(size_t)NROWS * HD / 8];
__device__ uint4 g_hh_lo [(size_t)NROWS * HD / 8];
__device__ uint4 g_h1_hi [(size_t)NROWS * HD / 8];
__device__ uint4 g_h1_lo [(size_t)NROWS * HD / 8];
__device__ uint4 g_S_hi  [(size_t)NB * HD / 8];
__device__ uint4 g_S_lo  [(size_t)NB * HD / 8];
__device__ uint4 g_ew_hi [(size_t)HD * DIN / 8];
__device__ uint4 g_ew_lo [(size_t)HD * DIN / 8];
__device__ uint4 g_fw_hi [(size_t)HD * HD / 8];
__device__ uint4 g_fw_lo [(size_t)HD * HD / 8];
__device__ uint4 g_wcat_hi[(size_t)H6 * HD / 8];  // [W_ih; W_hh] split
__device__ uint4 g_wcat_lo[(size_t)H6 * HD / 8];

__device__ __forceinline__ float sigmoidf_(float x) { return 1.0f / (1.0f + expf(-x)); }

__device__ __forceinline__ uint32_t smem_to_u32(const void* p) {
    uint32_t a;
    asm("{ .reg .u64 t; cvta.to.shared.u64 t, %1; cvt.u32.u64 %0, t; }" : "=r"(a) : "l"(p));
    return a;
}

#define SMEM_SWIZZLE_128B(off) ((off) ^ (((off) >> 3) & 0x70))

// ---------------------------------------------------------------------------
// mma / ldmatrix / cp.async primitives (baseline sm_80+ ISA)
// ---------------------------------------------------------------------------
__device__ __forceinline__ void mma_bf16(float* c, uint32_t a0, uint32_t a1, uint32_t a2,
                                         uint32_t a3, uint32_t b0, uint32_t b1) {
    asm volatile(
        "mma.sync.aligned.m16n8k16.row.col.f32.bf16.bf16.f32 "
        "{%0,%1,%2,%3}, {%4,%5,%6,%7}, {%8,%9}, {%0,%1,%2,%3};"
        : "+f"(c[0]), "+f"(c[1]), "+f"(c[2]), "+f"(c[3])
        : "r"(a0), "r"(a1), "r"(a2), "r"(a3), "r"(b0), "r"(b1));
}
__device__ __forceinline__ void ldm_x4(uint32_t* r, uint32_t addr) {
    asm volatile("ldmatrix.sync.aligned.m8n8.x4.shared.b16 {%0,%1,%2,%3}, [%4];"
                 : "=r"(r[0]), "=r"(r[1]), "=r"(r[2]), "=r"(r[3]) : "r"(addr));
}
__device__ __forceinline__ void ldm_x2(uint32_t* r, uint32_t addr) {
    asm volatile("ldmatrix.sync.aligned.m8n8.x2.shared.b16 {%0,%1}, [%2];"
                 : "=r"(r[0]), "=r"(r[1]) : "r"(addr));
}
__device__ __forceinline__ void cp16(uint32_t dst, const void* src) {
    asm volatile("cp.async.cg.shared.global [%0], [%1], 16;" :: "r"(dst), "l"(src));
}
#define CP_COMMIT()  asm volatile("cp.async.commit_group;")
#define CP_WAIT(n)   asm volatile("cp.async.wait_group %0;" :: "n"(n))

// hi/lo bf16 split helpers
__device__ __forceinline__ void split2(float a, float b, uint32_t& hi, uint32_t& lo) {
    __nv_bfloat16 ha = __float2bfloat16_rn(a);
    __nv_bfloat16 hb = __float2bfloat16_rn(b);
    float ra = a - __bfloat162float(ha);
    float rb = b - __bfloat162float(hb);
    __nv_bfloat16 la = __float2bfloat16_rn(ra);
    __nv_bfloat16 lb = __float2bfloat16_rn(rb);
    hi = (uint32_t)__bfloat16_as_ushort(ha) | ((uint32_t)__bfloat16_as_ushort(hb) << 16);
    lo = (uint32_t)__bfloat16_as_ushort(la) | ((uint32_t)__bfloat16_as_ushort(lb) << 16);
}

// ---------------------------------------------------------------------------
// fp32 -> bf16 hi/lo conversion
// ---------------------------------------------------------------------------
__global__ void convert_split(const float4* __restrict__ src,
                              uint2* __restrict__ hi, uint2* __restrict__ lo, int n4)
{
    const int i = blockIdx.x * blockDim.x + threadIdx.x;
    if (i >= n4) return;
    float4 v = src[i];
    uint2 H, L;
    split2(v.x, v.y, H.x, L.x);
    split2(v.z, v.w, H.y, L.y);
    hi[i] = H;
    lo[i] = L;
}

__global__ void bias_cat_kernel(const float* __restrict__ b_hh, float* __restrict__ bias_cat)
{
    const int i = blockIdx.x * blockDim.x + threadIdx.x;
    if (i < H6) bias_cat[i] = (i < H3) ? 0.f : b_hh[i - H3];
}

// ---------------------------------------------------------------------------
// bf16-split GEMM, cp.async 3-stage pipelined (R4 tile config):
//   C[N,M] = A[N,K] @ W[M,K]^T + bias  (A, W pre-split into hi/lo bf16)
// CTA tile 128x128, KC=64, 3 stages (192KB smem), 8 warps (2m x 4n).
// ---------------------------------------------------------------------------
#define ST_AH 0
#define ST_AL 16384
#define ST_WH 32768
#define ST_WL 49152
#define ST_SZ 65536
#define SM_TOTAL (3 * ST_SZ)

template <bool RELU, bool WF32, bool WSPLIT>
__global__ __launch_bounds__(256, 1)
void mma_gemm2(const __nv_bfloat16* __restrict__ Ahg, const __nv_bfloat16* __restrict__ Alg,
               const __nv_bfloat16* __restrict__ Whg, const __nv_bfloat16* __restrict__ Wlg,
               const float* __restrict__ bias, float* __restrict__ C,
               __nv_bfloat16* __restrict__ Ch, __nv_bfloat16* __restrict__ Cl,
               int K, int M)
{
    extern __shared__ char smem[];
    const uint32_t sb = smem_to_u32(smem);
    const int tid  = threadIdx.x;
    const int wid  = tid >> 5;
    const int lane = tid & 31;
    const int row0 = blockIdx.y * 128;
    const int col0 = blockIdx.x * 128;
    const int wm0  = (wid >> 2) * 64;
    const int wn0  = (wid & 3) * 32;

    const int a_row = wm0 + (lane & 15);
    const int a_kb  = ((lane >> 4) & 1) * 16;
    const int b_row = wn0 + (lane & 7);
    const int b_kb  = ((lane >> 3) & 1) * 16;

    // per-thread tile-load mapping (4 x 16B per array per stage)
    uint32_t sw[4];
    const __nv_bfloat16 *pA[4], *pAl[4], *pW[4], *pWl[4];
#pragma unroll
    for (int it = 0; it < 4; it++) {
        int g = tid + it * 256;
        int r = g >> 3, k0 = (g & 7) * 8;
        sw[it]  = SMEM_SWIZZLE_128B((uint32_t)(r * 128 + k0 * 2));
        pA[it]  = Ahg + (size_t)(row0 + r) * K + k0;
        pAl[it] = Alg + (size_t)(row0 + r) * K + k0;
        pW[it]  = Whg + (size_t)(col0 + r) * K + k0;
        pWl[it] = Wlg + (size_t)(col0 + r) * K + k0;
    }

    float acc[4][4][4];
#pragma unroll
    for (int i = 0; i < 4; i++)
#pragma unroll
        for (int j = 0; j < 4; j++)
#pragma unroll
            for (int q = 0; q < 4; q++) acc[i][j][q] = 0.f;

    const int nch = K >> 6;

    // prologue: prefetch chunks 0 and 1 (second group may be empty)
#pragma unroll
    for (int it = 0; it < 4; it++) {
        cp16(sb + ST_AH + sw[it], pA[it]);
        cp16(sb + ST_AL + sw[it], pAl[it]);
        cp16(sb + ST_WH + sw[it], pW[it]);
        cp16(sb + ST_WL + sw[it], pWl[it]);
    }
    CP_COMMIT();
    if (nch > 1) {
#pragma unroll
        for (int it = 0; it < 4; it++) {
            cp16(sb + ST_SZ + ST_AH + sw[it], pA[it]  + 64);
            cp16(sb + ST_SZ + ST_AL + sw[it], pAl[it] + 64);
            cp16(sb + ST_SZ + ST_WH + sw[it], pW[it]  + 64);
            cp16(sb + ST_SZ + ST_WL + sw[it], pWl[it] + 64);
        }
    }
    CP_COMMIT();

    for (int ch = 0; ch < nch; ch++) {
        const uint32_t sbase = sb + (uint32_t)(ch % 3) * ST_SZ;
        if (ch + 2 < nch) {
            const uint32_t nbase = sb + (uint32_t)((ch + 2) % 3) * ST_SZ;
            const int koff = (ch + 2) * 64;
#pragma unroll
            for (int it = 0; it < 4; it++) {
                cp16(nbase + ST_AH + sw[it], pA[it]  + koff);
                cp16(nbase + ST_AL + sw[it], pAl[it] + koff);
                cp16(nbase + ST_WH + sw[it], pW[it]  + koff);
                cp16(nbase + ST_WL + sw[it], pWl[it] + koff);
            }
            CP_COMMIT();
            CP_WAIT(2);
        } else if (ch + 1 < nch) {
            CP_WAIT(1);
        } else {
            CP_WAIT(0);
        }
        __syncthreads();

#pragma unroll
        for (int ks = 0; ks < 4; ks++) {
            uint32_t Ah[4][4], Al[4][4], Bh[4][2], Bl[4][2];
#pragma unroll
            for (int fm = 0; fm < 4; fm++) {
                uint32_t loc = SMEM_SWIZZLE_128B((uint32_t)((a_row + fm * 16) * 128 + ks * 32 + a_kb));
                ldm_x4(Ah[fm], sbase + ST_AH + loc);
                ldm_x4(Al[fm], sbase + ST_AL + loc);
            }
#pragma unroll
            for (int fn = 0; fn < 4; fn++) {
                uint32_t loc = SMEM_SWIZZLE_128B((uint32_t)((b_row + fn * 8) * 128 + ks * 32 + b_kb));
                ldm_x2(Bh[fn], sbase + ST_WH + loc);
                ldm_x2(Bl[fn], sbase + ST_WL + loc);
            }
#pragma unroll
            for (int fm = 0; fm < 4; fm++)
#pragma unroll
                for (int fn = 0; fn < 4; fn++) {
                    float* c = acc[fm][fn];
                    mma_bf16(c, Ah[fm][0], Ah[fm][1], Ah[fm][2], Ah[fm][3], Bh[fn][0], Bh[fn][1]);
                    mma_bf16(c, Ah[fm][0], Ah[fm][1], Ah[fm][2], Ah[fm][3], Bl[fn][0], Bl[fn][1]);
                    mma_bf16(c, Al[fm][0], Al[fm][1], Al[fm][2], Al[fm][3], Bh[fn][0], Bh[fn][1]);
                }
        }
        __syncthreads();
    }

    // epilogue
    const int gid  = lane >> 2;
    const int tid4 = lane & 3;
#pragma unroll
    for (int fn = 0; fn < 4; fn++) {
        const int col = col0 + wn0 + fn * 8 + 2 * tid4;
        const float b0 = bias[col], b1 = bias[col + 1];
#pragma unroll
        for (int fm = 0; fm < 4; fm++) {
            const int rlo = row0 + wm0 + fm * 16 + gid;
            float2 v0, v1;
            v0.x = acc[fm][fn][0] + b0;  v0.y = acc[fm][fn][1] + b1;
            v1.x = acc[fm][fn][2] + b0;  v1.y = acc[fm][fn][3] + b1;
            if (RELU) {
                v0.x = fmaxf(v0.x, 0.f); v0.y = fmaxf(v0.y, 0.f);
                v1.x = fmaxf(v1.x, 0.f); v1.y = fmaxf(v1.y, 0.f);
            }
            if (WF32) {
                *reinterpret_cast<float2*>(C + (size_t)rlo * M + col)       = v0;
                *reinterpret_cast<float2*>(C + (size_t)(rlo + 8) * M + col) = v1;
            }
            if (WSPLIT) {
                uint32_t h0, l0, h1, l1;
                split2(v0.x, v0.y, h0, l0);
                split2(v1.x, v1.y, h1, l1);
                *reinterpret_cast<uint32_t*>(Ch + (size_t)rlo * M + col)       = h0;
                *reinterpret_cast<uint32_t*>(Cl + (size_t)rlo * M + col)       = l0;
                *reinterpret_cast<uint32_t*>(Ch + (size_t)(rlo + 8) * M + col) = h1;
                *reinterpret_cast<uint32_t*>(Cl + (size_t)(rlo + 8) * M + col) = l1;
            }
        }
    }
}

// ---------------------------------------------------------------------------
// GRU gates k=0 (x==0 -> gi == b_ih): writes h1 fp32 AND h1 hi/lo bf16.
// ---------------------------------------------------------------------------
__global__ void gates0_kernel(const float* __restrict__ gh,
                              const float* __restrict__ b_ih,
                              const float* __restrict__ h,
                              float* __restrict__ h1,
                              uint2* __restrict__ h1_hi, uint2* __restrict__ h1_lo)
{
    const int idx = blockIdx.x * blockDim.x + threadIdx.x;  // over NROWS*64
    const int i = idx >> 6;
    const int q = idx & 63;
    const float4* ghr = reinterpret_cast<const float4*>(gh + (size_t)i * H3);
    const float4* bi  = reinterpret_cast<const float4*>(b_ih);
    float4 gr = ghr[q], gz = ghr[64 + q], gn = ghr[128 + q];
    float4 br = bi[q],  bz = bi[64 + q],  bn = bi[128 + q];
    float4 hh = reinterpret_cast<const float4*>(h)[(size_t)i * 64 + q];
    float4 o;
    { float r = sigmoidf_(br.x + gr.x), z = sigmoidf_(bz.x + gz.x);
      float n = tanhf(bn.x + r * gn.x); o.x = (1.f - z) * n + z * hh.x; }
    { float r = sigmoidf_(br.y + gr.y), z = sigmoidf_(bz.y + gz.y);
      float n = tanhf(bn.y + r * gn.y); o.y = (1.f - z) * n + z * hh.y; }
    { float r = sigmoidf_(br.z + gr.z), z = sigmoidf_(bz.z + gz.z);
      float n = tanhf(bn.z + r * gn.z); o.z = (1.f - z) * n + z * hh.z; }
    { float r = sigmoidf_(br.w + gr.w), z = sigmoidf_(bz.w + gz.w);
      float n = tanhf(bn.w + r * gn.w); o.w = (1.f - z) * n + z * hh.w; }
    reinterpret_cast<float4*>(h1)[(size_t)i * 64 + q] = o;
    uint2 H, L;
    split2(o.x, o.y, H.x, L.x);
    split2(o.z, o.w, H.y, L.y);
    h1_hi[(size_t)i * 64 + q] = H;
    h1_lo[(size_t)i * 64 + q] = L;
}

// ---------------------------------------------------------------------------
// Per-batch agent sum: S[b,:] = sum_a h1[b,a,:], written as bf16 hi/lo
// ---------------------------------------------------------------------------
__global__ void commS_kernel(const float* __restrict__ h1,
                             __nv_bfloat16* __restrict__ S_hi,
                             __nv_bfloat16* __restrict__ S_lo)
{
    const int b = blockIdx.x;
    const int j = threadIdx.x;
    const float* base = h1 + (size_t)b * NA * HD + j;
    float s = 0.f;
#pragma unroll
    for (int a = 0; a < NA; a++) s += base[a * HD];
    __nv_bfloat16 hv = __float2bfloat16_rn(s);
    S_hi[(size_t)b * HD + j] = hv;
    S_lo[(size_t)b * HD + j] = __float2bfloat16_rn(s - __bfloat162float(hv));
}

// ---------------------------------------------------------------------------
// GRU gates k=1 + decoder.  gi = (Sg[b] - Gih[i]) / NA + b_ih.
// gcat row layout: [Gih (768) | ghh (768, includes b_hh)]
// ---------------------------------------------------------------------------
__global__ void gates1_dec_kernel(const float* __restrict__ gcat,
                                  const float* __restrict__ Sg,
                                  const float* __restrict__ b_ih,
                                  const float* __restrict__ h1,
                                  const float* __restrict__ dec_W,
                                  const float* __restrict__ dec_b,
                                  float* __restrict__ out)
{
    const int tid = threadIdx.x;
    const int i = blockIdx.x * 4 + (tid >> 6);
    const int b = i >> 5;              // batch index (NA = 32)
    const int q = tid & 63;
    const float4* gc = reinterpret_cast<const float4*>(gcat + (size_t)i * H6);  // 384 f4
    const float4* sg = reinterpret_cast<const float4*>(Sg + (size_t)b * H3);    // 192 f4
    const float4* bi = reinterpret_cast<const float4*>(b_ih);
    const float inv = 1.f / (float)NA;

    float4 gih_r = gc[q], gih_z = gc[64 + q], gih_n = gc[128 + q];
    float4 sg_r = sg[q],  sg_z = sg[64 + q],  sg_n = sg[128 + q];
    float4 bi_r = bi[q],  bi_z = bi[64 + q],  bi_n = bi[128 + q];
    float4 ir, iz, in_;
    ir.x = (sg_r.x - gih_r.x) * inv + bi_r.x;  ir.y = (sg_r.y - gih_r.y) * inv + bi_r.y;
    ir.z = (sg_r.z - gih_r.z) * inv + bi_r.z;  ir.w = (sg_r.w - gih_r.w) * inv + bi_r.w;
    iz.x = (sg_z.x - gih_z.x) * inv + bi_z.x;  iz.y = (sg_z.y - gih_z.y) * inv + bi_z.y;
    iz.z = (sg_z.z - gih_z.z) * inv + bi_z.z;  iz.w = (sg_z.w - gih_z.w) * inv + bi_z.w;
    in_.x = (sg_n.x - gih_n.x) * inv + bi_n.x; in_.y = (sg_n.y - gih_n.y) * inv + bi_n.y;
    in_.z = (sg_n.z - gih_n.z) * inv + bi_n.z; in_.w = (sg_n.w - gih_n.w) * inv + bi_n.w;

    float4 hr = gc[192 + q], hz = gc[256 + q], hn = gc[320 + q];
    float4 hp = reinterpret_cast<const float4*>(h1)[(size_t)i * 64 + q];
    float4 dw = reinterpret_cast<const float4*>(dec_W)[q];

    float p = 0.f;
    { float r = sigmoidf_(ir.x + hr.x), z = sigmoidf_(iz.x + hz.x);
      float n = tanhf(in_.x + r * hn.x); p += ((1.f - z) * n + z * hp.x) * dw.x; }
    { float r = sigmoidf_(ir.y + hr.y), z = sigmoidf_(iz.y + hz.y);
      float n = tanhf(in_.y + r * hn.y); p += ((1.f - z) * n + z * hp.y) * dw.y; }
    { float r = sigmoidf_(ir.z + hr.z), z = sigmoidf_(iz.z + hz.z);
      float n = tanhf(in_.z + r * hn.z); p += ((1.f - z) * n + z * hp.z) * dw.z; }
    { float r = sigmoidf_(ir.w + hr.w), z = sigmoidf_(iz.w + hz.w);
      float n = tanhf(in_.w + r * hn.w); p += ((1.f - z) * n + z * hp.w) * dw.w; }
#pragma unroll
    for (int o = 16; o > 0; o >>= 1) p += __shfl_down_sync(0xffffffffu, p, o);
    __shared__ float red[8];
    if ((tid & 31) == 0) red[tid >> 5] = p;
    __syncthreads();
    if (tid < 4) out[blockIdx.x * 4 + tid] = red[2 * tid] + red[2 * tid + 1] + dec_b[0];
}

// ---------------------------------------------------------------------------
// Launch
// ---------------------------------------------------------------------------
extern "C" void kernel_launch(void* const* d_in, const int* in_sizes, int n_in,
                              void* d_out, int out_size)
{
    const float* obs    = (const float*)d_in[0];
    const float* enc_W  = (const float*)d_in[2];
    const float* enc_b  = (const float*)d_in[3];
    const float* fobs_W = (const float*)d_in[4];
    const float* fobs_b = (const float*)d_in[5];
    const float* W_ih   = (const float*)d_in[6];
    const float* b_ih   = (const float*)d_in[7];
    const float* W_hh   = (const float*)d_in[8];
    const float* b_hh   = (const float*)d_in[9];
    const float* dec_W  = (const float*)d_in[10];
    const float* dec_b  = (const float*)d_in[11];
    float* out = (float*)d_out;

    float *h, *h1, *gh, *gcat, *sg, *bias_cat;
    cudaGetSymbolAddress((void**)&h,    g_h);
    cudaGetSymbolAddress((void**)&h1,   g_h1);
    cudaGetSymbolAddress((void**)&gh,   g_gh);
    cudaGetSymbolAddress((void**)&gcat, g_gcat);
    cudaGetSymbolAddress((void**)&sg,   g_sg);
    cudaGetSymbolAddress((void**)&bias_cat, g_bias_cat);

    void *obs_hi, *obs_lo, *e_hi, *e_lo, *hh_hi, *hh_lo, *h1_hi, *h1_lo;
    void *S_hi, *S_lo, *ew_hi, *ew_lo, *fw_hi, *fw_lo, *wcat_hi, *wcat_lo;
    cudaGetSymbolAddress(&obs_hi, g_obs_hi);  cudaGetSymbolAddress(&obs_lo, g_obs_lo);
    cudaGetSymbolAddress(&e_hi,  g_e_hi);     cudaGetSymbolAddress(&e_lo,  g_e_lo);
    cudaGetSymbolAddress(&hh_hi, g_hh_hi);    cudaGetSymbolAddress(&hh_lo, g_hh_lo);
    cudaGetSymbolAddress(&h1_hi, g_h1_hi);    cudaGetSymbolAddress(&h1_lo, g_h1_lo);
    cudaGetSymbolAddress(&S_hi,  g_S_hi);     cudaGetSymbolAddress(&S_lo,  g_S_lo);
    cudaGetSymbolAddress(&ew_hi, g_ew_hi);    cudaGetSymbolAddress(&ew_lo, g_ew_lo);
    cudaGetSymbolAddress(&fw_hi, g_fw_hi);    cudaGetSymbolAddress(&fw_lo, g_fw_lo);
    cudaGetSymbolAddress(&wcat_hi, g_wcat_hi); cudaGetSymbolAddress(&wcat_lo, g_wcat_lo);

    cudaFuncSetAttribute(mma_gemm2<true , false, true >, cudaFuncAttributeMaxDynamicSharedMemorySize, SM_TOTAL);
    cudaFuncSetAttribute(mma_gemm2<false, true , true >, cudaFuncAttributeMaxDynamicSharedMemorySize, SM_TOTAL);
    cudaFuncSetAttribute(mma_gemm2<false, true , false>, cudaFuncAttributeMaxDynamicSharedMemorySize, SM_TOTAL);

    typedef const __nv_bfloat16* bfp;
    typedef __nv_bfloat16* bfpm;

    // 0) pre-split obs + weights to bf16 hi/lo; W_ih/W_hh concatenated
    convert_split<<<(NROWS * DIN / 4 + 255) / 256, 256>>>((const float4*)obs, (uint2*)obs_hi, (uint2*)obs_lo, NROWS * DIN / 4);
    convert_split<<<(HD * DIN / 4 + 255) / 256, 256>>>((const float4*)enc_W,  (uint2*)ew_hi, (uint2*)ew_lo, HD * DIN / 4);
    convert_split<<<(HD * HD  / 4 + 255) / 256, 256>>>((const float4*)fobs_W, (uint2*)fw_hi, (uint2*)fw_lo, HD * HD / 4);
    convert_split<<<(H3 * HD  / 4 + 255) / 256, 256>>>((const float4*)W_ih,
        (uint2*)wcat_hi, (uint2*)wcat_lo, H3 * HD / 4);
    convert_split<<<(H3 * HD  / 4 + 255) / 256, 256>>>((const float4*)W_hh,
        (uint2*)wcat_hi + (size_t)H3 * HD / 4, (uint2*)wcat_lo + (size_t)H3 * HD / 4, H3 * HD / 4);
    bias_cat_kernel<<<(H6 + 255) / 256, 256>>>(b_hh, bias_cat);

    const dim3 blk(256);
    const int rowBlocks = NROWS / 128;  // 512
    const __nv_bfloat16* whh_hi = (bfp)wcat_hi + (size_t)H3 * HD;
    const __nv_bfloat16* whh_lo = (bfp)wcat_lo + (size_t)H3 * HD;

    // 1) e = relu(obs @ enc_W^T + enc_b) -> e_hi/e_lo       K=128, M=256
    mma_gemm2<true, false, true><<<dim3(2, rowBlocks), blk, SM_TOTAL>>>(
        (bfp)obs_hi, (bfp)obs_lo, (bfp)ew_hi, (bfp)ew_lo, enc_b,
        nullptr, (bfpm)e_hi, (bfpm)e_lo, DIN, HD);
    // 2) h = e @ fobs_W^T + fobs_b -> h fp32 + h_hi/h_lo    K=256, M=256
    mma_gemm2<false, true, true><<<dim3(2, rowBlocks), blk, SM_TOTAL>>>(
        (bfp)e_hi, (bfp)e_lo, (bfp)fw_hi, (bfp)fw_lo, fobs_b,
        h, (bfpm)hh_hi, (bfpm)hh_lo, HD, HD);
    // 3) gh = h @ W_hh^T + b_hh                             K=256, M=768
    mma_gemm2<false, true, false><<<dim3(6, rowBlocks), blk, SM_TOTAL>>>(
        (bfp)hh_hi, (bfp)hh_lo, whh_hi, whh_lo, b_hh,
        gh, nullptr, nullptr, HD, H3);
    // 4) GRU k=0 gates -> h1 (fp32 + hi/lo)
    gates0_kernel<<<(NROWS * 64) / 256, 256>>>(gh, b_ih, h, h1, (uint2*)h1_hi, (uint2*)h1_lo);
    // 5) S[b] = sum_a h1[b,a]  -> S_hi/S_lo
    commS_kernel<<<NB, HD>>>(h1, (bfpm)S_hi, (bfpm)S_lo);
    // 6) Sg = S @ W_ih^T  (bias = zeros half of bias_cat)   rows=2048, M=768
    mma_gemm2<false, true, false><<<dim3(6, NB / 128), blk, SM_TOTAL>>>(
        (bfp)S_hi, (bfp)S_lo, (bfp)wcat_hi, (bfp)wcat_lo, bias_cat,
        sg, nullptr, nullptr, HD, H3);
    // 7) gcat = h1 @ [W_ih; W_hh]^T + [0; b_hh]             M=1536
    mma_gemm2<false, true, false><<<dim3(12, rowBlocks), blk, SM_TOTAL>>>(
        (bfp)h1_hi, (bfp)h1_lo, (bfp)wcat_hi, (bfp)wcat_lo, bias_cat,
        gcat, nullptr, nullptr, HD, H6);
    // 8) GRU k=1 gates + decoder -> out
    gates1_dec_kernel<<<NROWS / 4, 256>>>(gcat, sg, b_ih, h1, dec_W, dec_b, out);
}

// round 7
// speedup vs baseline: 1.9622x; 1.7999x over previous
#include <cuda_runtime.h>
#include <cuda_fp16.h>
#include <math.h>
#include <stdint.h>

// Problem constants (B=2048, A=32, D=128, H=256)
#define NB    2048
#define NA    32
#define NROWS (NB * NA)   // 65536
#define DIN   128
#define HD    256
#define H3    768
#define H6    1536

// ---------------------------------------------------------------------------
// Scratch (__device__ globals; uint4 arrays guarantee 16B alignment)
// ---------------------------------------------------------------------------
__device__ float g_h   [(size_t)NROWS * HD];
__device__ float g_h1  [(size_t)NROWS * HD];
__device__ float g_gh  [(size_t)NROWS * H3];    // k=0 gh
__device__ float g_gcat[(size_t)NROWS * H6];    // k=1: [h1@W_ih | h1@W_hh + b_hh]
__device__ float g_sg  [(size_t)NB * H3];       // S @ W_ih^T
__device__ float g_bias_cat[H6];

// fp16 operand buffers
__device__ uint4 g_obs_f [(size_t)NROWS * DIN / 8];
__device__ uint4 g_e_f   [(size_t)NROWS * HD / 8];
__device__ uint4 g_hh_f  [(size_t)NROWS * HD / 8];
__device__ uint4 g_h1_f  [(size_t)NROWS * HD / 8];
__device__ uint4 g_S_f   [(size_t)NB * HD / 8];
__device__ uint4 g_ew_f  [(size_t)HD * DIN / 8];
__device__ uint4 g_fw_f  [(size_t)HD * HD / 8];
__device__ uint4 g_wcat_f[(size_t)H6 * HD / 8];  // [W_ih; W_hh] fp16

__device__ __forceinline__ float sigmoidf_(float x) { return 1.0f / (1.0f + expf(-x)); }

__device__ __forceinline__ uint32_t smem_to_u32(const void* p) {
    uint32_t a;
    asm("{ .reg .u64 t; cvta.to.shared.u64 t, %1; cvt.u32.u64 %0, t; }" : "=r"(a) : "l"(p));
    return a;
}

#define SMEM_SWIZZLE_128B(off) ((off) ^ (((off) >> 3) & 0x70))

// ---------------------------------------------------------------------------
// mma / ldmatrix / cp.async primitives (baseline sm_80+ ISA)
// ---------------------------------------------------------------------------
__device__ __forceinline__ void mma_f16(float* c, uint32_t a0, uint32_t a1, uint32_t a2,
                                        uint32_t a3, uint32_t b0, uint32_t b1) {
    asm volatile(
        "mma.sync.aligned.m16n8k16.row.col.f32.f16.f16.f32 "
        "{%0,%1,%2,%3}, {%4,%5,%6,%7}, {%8,%9}, {%0,%1,%2,%3};"
        : "+f"(c[0]), "+f"(c[1]), "+f"(c[2]), "+f"(c[3])
        : "r"(a0), "r"(a1), "r"(a2), "r"(a3), "r"(b0), "r"(b1));
}
__device__ __forceinline__ void ldm_x4(uint32_t* r, uint32_t addr) {
    asm volatile("ldmatrix.sync.aligned.m8n8.x4.shared.b16 {%0,%1,%2,%3}, [%4];"
                 : "=r"(r[0]), "=r"(r[1]), "=r"(r[2]), "=r"(r[3]) : "r"(addr));
}
__device__ __forceinline__ void ldm_x2(uint32_t* r, uint32_t addr) {
    asm volatile("ldmatrix.sync.aligned.m8n8.x2.shared.b16 {%0,%1}, [%2];"
                 : "=r"(r[0]), "=r"(r[1]) : "r"(addr));
}
__device__ __forceinline__ void cp16(uint32_t dst, const void* src) {
    asm volatile("cp.async.cg.shared.global [%0], [%1], 16;" :: "r"(dst), "l"(src));
}
#define CP_COMMIT()  asm volatile("cp.async.commit_group;")
#define CP_WAIT(n)   asm volatile("cp.async.wait_group %0;" :: "n"(n))

__device__ __forceinline__ uint32_t pack_h2(float a, float b) {
    __half2 h = __floats2half2_rn(a, b);
    return *reinterpret_cast<uint32_t*>(&h);
}

// ---------------------------------------------------------------------------
// fp32 -> fp16 conversion
// ---------------------------------------------------------------------------
__global__ void convert_h(const float4* __restrict__ src, uint2* __restrict__ dst, int n4)
{
    const int i = blockIdx.x * blockDim.x + threadIdx.x;
    if (i >= n4) return;
    float4 v = src[i];
    uint2 o;
    o.x = pack_h2(v.x, v.y);
    o.y = pack_h2(v.z, v.w);
    dst[i] = o;
}

__global__ void bias_cat_kernel(const float* __restrict__ b_hh, float* __restrict__ bias_cat)
{
    const int i = blockIdx.x * blockDim.x + threadIdx.x;
    if (i < H6) bias_cat[i] = (i < H3) ? 0.f : b_hh[i - H3];
}

// ---------------------------------------------------------------------------
// fp16 single-pass GEMM, cp.async 3-stage, 2 CTAs/SM:
//   C[N,M] = A[N,K] @ W[M,K]^T + bias  (A, W fp16; fp32 accumulate)
// CTA tile 128x128, KC=64, 3 stages (96KB smem), 8 warps (2m x 4n).
// ---------------------------------------------------------------------------
#define ST_AH 0
#define ST_WH 16384
#define ST_SZ 32768
#define SM_TOTAL (3 * ST_SZ)

template <bool RELU, bool WF32, bool WHALF>
__global__ __launch_bounds__(256, 2)
void mma_gemmh(const __half* __restrict__ Ag, const __half* __restrict__ Wg,
               const float* __restrict__ bias, float* __restrict__ C,
               __half* __restrict__ Ch, int K, int M)
{
    extern __shared__ char smem[];
    const uint32_t sb = smem_to_u32(smem);
    const int tid  = threadIdx.x;
    const int wid  = tid >> 5;
    const int lane = tid & 31;
    const int row0 = blockIdx.y * 128;
    const int col0 = blockIdx.x * 128;
    const int wm0  = (wid >> 2) * 64;
    const int wn0  = (wid & 3) * 32;

    const int a_row = wm0 + (lane & 15);
    const int a_kb  = ((lane >> 4) & 1) * 16;
    const int b_row = wn0 + (lane & 7);
    const int b_kb  = ((lane >> 3) & 1) * 16;

    // per-thread tile-load mapping (4 x 16B per array per stage)
    uint32_t sw[4];
    const __half *pA[4], *pW[4];
#pragma unroll
    for (int it = 0; it < 4; it++) {
        int g = tid + it * 256;
        int r = g >> 3, k0 = (g & 7) * 8;
        sw[it] = SMEM_SWIZZLE_128B((uint32_t)(r * 128 + k0 * 2));
        pA[it] = Ag + (size_t)(row0 + r) * K + k0;
        pW[it] = Wg + (size_t)(col0 + r) * K + k0;
    }

    float acc[4][4][4];
#pragma unroll
    for (int i = 0; i < 4; i++)
#pragma unroll
        for (int j = 0; j < 4; j++)
#pragma unroll
            for (int q = 0; q < 4; q++) acc[i][j][q] = 0.f;

    const int nch = K >> 6;

    // prologue: prefetch chunks 0 and 1
#pragma unroll
    for (int it = 0; it < 4; it++) {
        cp16(sb + ST_AH + sw[it], pA[it]);
        cp16(sb + ST_WH + sw[it], pW[it]);
    }
    CP_COMMIT();
    if (nch > 1) {
#pragma unroll
        for (int it = 0; it < 4; it++) {
            cp16(sb + ST_SZ + ST_AH + sw[it], pA[it] + 64);
            cp16(sb + ST_SZ + ST_WH + sw[it], pW[it] + 64);
        }
    }
    CP_COMMIT();

    for (int ch = 0; ch < nch; ch++) {
        const uint32_t sbase = sb + (uint32_t)(ch % 3) * ST_SZ;
        if (ch + 2 < nch) {
            const uint32_t nbase = sb + (uint32_t)((ch + 2) % 3) * ST_SZ;
            const int koff = (ch + 2) * 64;
#pragma unroll
            for (int it = 0; it < 4; it++) {
                cp16(nbase + ST_AH + sw[it], pA[it] + koff);
                cp16(nbase + ST_WH + sw[it], pW[it] + koff);
            }
            CP_COMMIT();
            CP_WAIT(2);
        } else if (ch + 1 < nch) {
            CP_WAIT(1);
        } else {
            CP_WAIT(0);
        }
        __syncthreads();

#pragma unroll
        for (int ks = 0; ks < 4; ks++) {
            uint32_t Af[4][4], Bf[4][2];
#pragma unroll
            for (int fm = 0; fm < 4; fm++) {
                uint32_t loc = SMEM_SWIZZLE_128B((uint32_t)((a_row + fm * 16) * 128 + ks * 32 + a_kb));
                ldm_x4(Af[fm], sbase + ST_AH + loc);
            }
#pragma unroll
            for (int fn = 0; fn < 4; fn++) {
                uint32_t loc = SMEM_SWIZZLE_128B((uint32_t)((b_row + fn * 8) * 128 + ks * 32 + b_kb));
                ldm_x2(Bf[fn], sbase + ST_WH + loc);
            }
#pragma unroll
            for (int fm = 0; fm < 4; fm++)
#pragma unroll
                for (int fn = 0; fn < 4; fn++)
                    mma_f16(acc[fm][fn], Af[fm][0], Af[fm][1], Af[fm][2], Af[fm][3],
                            Bf[fn][0], Bf[fn][1]);
        }
        __syncthreads();
    }

    // epilogue
    const int gid  = lane >> 2;
    const int tid4 = lane & 3;
#pragma unroll
    for (int fn = 0; fn < 4; fn++) {
        const int col = col0 + wn0 + fn * 8 + 2 * tid4;
        const float b0 = bias[col], b1 = bias[col + 1];
#pragma unroll
        for (int fm = 0; fm < 4; fm++) {
            const int rlo = row0 + wm0 + fm * 16 + gid;
            float2 v0, v1;
            v0.x = acc[fm][fn][0] + b0;  v0.y = acc[fm][fn][1] + b1;
            v1.x = acc[fm][fn][2] + b0;  v1.y = acc[fm][fn][3] + b1;
            if (RELU) {
                v0.x = fmaxf(v0.x, 0.f); v0.y = fmaxf(v0.y, 0.f);
                v1.x = fmaxf(v1.x, 0.f); v1.y = fmaxf(v1.y, 0.f);
            }
            if (WF32) {
                *reinterpret_cast<float2*>(C + (size_t)rlo * M + col)       = v0;
                *reinterpret_cast<float2*>(C + (size_t)(rlo + 8) * M + col) = v1;
            }
            if (WHALF) {
                *reinterpret_cast<uint32_t*>(Ch + (size_t)rlo * M + col)       = pack_h2(v0.x, v0.y);
                *reinterpret_cast<uint32_t*>(Ch + (size_t)(rlo + 8) * M + col) = pack_h2(v1.x, v1.y);
            }
        }
    }
}

// ---------------------------------------------------------------------------
// GRU gates k=0 (x==0 -> gi == b_ih): writes h1 fp32 AND h1 fp16.
// ---------------------------------------------------------------------------
__global__ void gates0_kernel(const float* __restrict__ gh,
                              const float* __restrict__ b_ih,
                              const float* __restrict__ h,
                              float* __restrict__ h1,
                              uint2* __restrict__ h1_f)
{
    const int idx = blockIdx.x * blockDim.x + threadIdx.x;  // over NROWS*64
    const int i = idx >> 6;
    const int q = idx & 63;
    const float4* ghr = reinterpret_cast<const float4*>(gh + (size_t)i * H3);
    const float4* bi  = reinterpret_cast<const float4*>(b_ih);
    float4 gr = ghr[q], gz = ghr[64 + q], gn = ghr[128 + q];
    float4 br = bi[q],  bz = bi[64 + q],  bn = bi[128 + q];
    float4 hh = reinterpret_cast<const float4*>(h)[(size_t)i * 64 + q];
    float4 o;
    { float r = sigmoidf_(br.x + gr.x), z = sigmoidf_(bz.x + gz.x);
      float n = tanhf(bn.x + r * gn.x); o.x = (1.f - z) * n + z * hh.x; }
    { float r = sigmoidf_(br.y + gr.y), z = sigmoidf_(bz.y + gz.y);
      float n = tanhf(bn.y + r * gn.y); o.y = (1.f - z) * n + z * hh.y; }
    { float r = sigmoidf_(br.z + gr.z), z = sigmoidf_(bz.z + gz.z);
      float n = tanhf(bn.z + r * gn.z); o.z = (1.f - z) * n + z * hh.z; }
    { float r = sigmoidf_(br.w + gr.w), z = sigmoidf_(bz.w + gz.w);
      float n = tanhf(bn.w + r * gn.w); o.w = (1.f - z) * n + z * hh.w; }
    reinterpret_cast<float4*>(h1)[(size_t)i * 64 + q] = o;
    uint2 P;
    P.x = pack_h2(o.x, o.y);
    P.y = pack_h2(o.z, o.w);
    h1_f[(size_t)i * 64 + q] = P;
}

// ---------------------------------------------------------------------------
// Per-batch agent sum: S[b,:] = sum_a h1[b,a,:], written as fp16
// ---------------------------------------------------------------------------
__global__ void commS_kernel(const float* __restrict__ h1, __half* __restrict__ S_f)
{
    const int b = blockIdx.x;
    const int j = threadIdx.x;
    const float* base = h1 + (size_t)b * NA * HD + j;
    float s = 0.f;
#pragma unroll
    for (int a = 0; a < NA; a++) s += base[a * HD];
    S_f[(size_t)b * HD + j] = __float2half_rn(s);
}

// ---------------------------------------------------------------------------
// GRU gates k=1 + decoder.  gi = (Sg[b] - Gih[i]) / NA + b_ih.
// gcat row layout: [Gih (768) | ghh (768, includes b_hh)]
// ---------------------------------------------------------------------------
__global__ void gates1_dec_kernel(const float* __restrict__ gcat,
                                  const float* __restrict__ Sg,
                                  const float* __restrict__ b_ih,
                                  const float* __restrict__ h1,
                                  const float* __restrict__ dec_W,
                                  const float* __restrict__ dec_b,
                                  float* __restrict__ out)
{
    const int tid = threadIdx.x;
    const int i = blockIdx.x * 4 + (tid >> 6);
    const int b = i >> 5;              // batch index (NA = 32)
    const int q = tid & 63;
    const float4* gc = reinterpret_cast<const float4*>(gcat + (size_t)i * H6);
    const float4* sg = reinterpret_cast<const float4*>(Sg + (size_t)b * H3);
    const float4* bi = reinterpret_cast<const float4*>(b_ih);
    const float inv = 1.f / (float)NA;

    float4 gih_r = gc[q], gih_z = gc[64 + q], gih_n = gc[128 + q];
    float4 sg_r = sg[q],  sg_z = sg[64 + q],  sg_n = sg[128 + q];
    float4 bi_r = bi[q],  bi_z = bi[64 + q],  bi_n = bi[128 + q];
    float4 ir, iz, in_;
    ir.x = (sg_r.x - gih_r.x) * inv + bi_r.x;  ir.y = (sg_r.y - gih_r.y) * inv + bi_r.y;
    ir.z = (sg_r.z - gih_r.z) * inv + bi_r.z;  ir.w = (sg_r.w - gih_r.w) * inv + bi_r.w;
    iz.x = (sg_z.x - gih_z.x) * inv + bi_z.x;  iz.y = (sg_z.y - gih_z.y) * inv + bi_z.y;
    iz.z = (sg_z.z - gih_z.z) * inv + bi_z.z;  iz.w = (sg_z.w - gih_z.w) * inv + bi_z.w;
    in_.x = (sg_n.x - gih_n.x) * inv + bi_n.x; in_.y = (sg_n.y - gih_n.y) * inv + bi_n.y;
    in_.z = (sg_n.z - gih_n.z) * inv + bi_n.z; in_.w = (sg_n.w - gih_n.w) * inv + bi_n.w;

    float4 hr = gc[192 + q], hz = gc[256 + q], hn = gc[320 + q];
    float4 hp = reinterpret_cast<const float4*>(h1)[(size_t)i * 64 + q];
    float4 dw = reinterpret_cast<const float4*>(dec_W)[q];

    float p = 0.f;
    { float r = sigmoidf_(ir.x + hr.x), z = sigmoidf_(iz.x + hz.x);
      float n = tanhf(in_.x + r * hn.x); p += ((1.f - z) * n + z * hp.x) * dw.x; }
    { float r = sigmoidf_(ir.y + hr.y), z = sigmoidf_(iz.y + hz.y);
      float n = tanhf(in_.y + r * hn.y); p += ((1.f - z) * n + z * hp.y) * dw.y; }
    { float r = sigmoidf_(ir.z + hr.z), z = sigmoidf_(iz.z + hz.z);
      float n = tanhf(in_.z + r * hn.z); p += ((1.f - z) * n + z * hp.z) * dw.z; }
    { float r = sigmoidf_(ir.w + hr.w), z = sigmoidf_(iz.w + hz.w);
      float n = tanhf(in_.w + r * hn.w); p += ((1.f - z) * n + z * hp.w) * dw.w; }
#pragma unroll
    for (int o = 16; o > 0; o >>= 1) p += __shfl_down_sync(0xffffffffu, p, o);
    __shared__ float red[8];
    if ((tid & 31) == 0) red[tid >> 5] = p;
    __syncthreads();
    if (tid < 4) out[blockIdx.x * 4 + tid] = red[2 * tid] + red[2 * tid + 1] + dec_b[0];
}

// ---------------------------------------------------------------------------
// Launch
// ---------------------------------------------------------------------------
extern "C" void kernel_launch(void* const* d_in, const int* in_sizes, int n_in,
                              void* d_out, int out_size)
{
    const float* obs    = (const float*)d_in[0];
    const float* enc_W  = (const float*)d_in[2];
    const float* enc_b  = (const float*)d_in[3];
    const float* fobs_W = (const float*)d_in[4];
    const float* fobs_b = (const float*)d_in[5];
    const float* W_ih   = (const float*)d_in[6];
    const float* b_ih   = (const float*)d_in[7];
    const float* W_hh   = (const float*)d_in[8];
    const float* b_hh   = (const float*)d_in[9];
    const float* dec_W  = (const float*)d_in[10];
    const float* dec_b  = (const float*)d_in[11];
    float* out = (float*)d_out;

    float *h, *h1, *gh, *gcat, *sg, *bias_cat;
    cudaGetSymbolAddress((void**)&h,    g_h);
    cudaGetSymbolAddress((void**)&h1,   g_h1);
    cudaGetSymbolAddress((void**)&gh,   g_gh);
    cudaGetSymbolAddress((void**)&gcat, g_gcat);
    cudaGetSymbolAddress((void**)&sg,   g_sg);
    cudaGetSymbolAddress((void**)&bias_cat, g_bias_cat);

    void *obs_f, *e_f, *hh_f, *h1_f, *S_f, *ew_f, *fw_f, *wcat_f;
    cudaGetSymbolAddress(&obs_f, g_obs_f);
    cudaGetSymbolAddress(&e_f,   g_e_f);
    cudaGetSymbolAddress(&hh_f,  g_hh_f);
    cudaGetSymbolAddress(&h1_f,  g_h1_f);
    cudaGetSymbolAddress(&S_f,   g_S_f);
    cudaGetSymbolAddress(&ew_f,  g_ew_f);
    cudaGetSymbolAddress(&fw_f,  g_fw_f);
    cudaGetSymbolAddress(&wcat_f, g_wcat_f);

    cudaFuncSetAttribute(mma_gemmh<true , false, true >, cudaFuncAttributeMaxDynamicSharedMemorySize, SM_TOTAL);
    cudaFuncSetAttribute(mma_gemmh<false, true , true >, cudaFuncAttributeMaxDynamicSharedMemorySize, SM_TOTAL);
    cudaFuncSetAttribute(mma_gemmh<false, true , false>, cudaFuncAttributeMaxDynamicSharedMemorySize, SM_TOTAL);

    typedef const __half* hfp;
    typedef __half* hfpm;

    // 0) convert obs + weights to fp16; W_ih/W_hh concatenated
    convert_h<<<(NROWS * DIN / 4 + 255) / 256, 256>>>((const float4*)obs, (uint2*)obs_f, NROWS * DIN / 4);
    convert_h<<<(HD * DIN / 4 + 255) / 256, 256>>>((const float4*)enc_W,  (uint2*)ew_f, HD * DIN / 4);
    convert_h<<<(HD * HD  / 4 + 255) / 256, 256>>>((const float4*)fobs_W, (uint2*)fw_f, HD * HD / 4);
    convert_h<<<(H3 * HD  / 4 + 255) / 256, 256>>>((const float4*)W_ih,   (uint2*)wcat_f, H3 * HD / 4);
    convert_h<<<(H3 * HD  / 4 + 255) / 256, 256>>>((const float4*)W_hh,
        (uint2*)wcat_f + (size_t)H3 * HD / 4, H3 * HD / 4);
    bias_cat_kernel<<<(H6 + 255) / 256, 256>>>(b_hh, bias_cat);

    const dim3 blk(256);
    const int rowBlocks = NROWS / 128;  // 512
    const __half* whh_f = (hfp)wcat_f + (size_t)H3 * HD;

    // 1) e = relu(obs @ enc_W^T + enc_b) -> e_f              K=128, M=256
    mma_gemmh<true, false, true><<<dim3(2, rowBlocks), blk, SM_TOTAL>>>(
        (hfp)obs_f, (hfp)ew_f, enc_b, nullptr, (hfpm)e_f, DIN, HD);
    // 2) h = e @ fobs_W^T + fobs_b -> h fp32 + hh_f           K=256, M=256
    mma_gemmh<false, true, true><<<dim3(2, rowBlocks), blk, SM_TOTAL>>>(
        (hfp)e_f, (hfp)fw_f, fobs_b, h, (hfpm)hh_f, HD, HD);
    // 3) gh = h @ W_hh^T + b_hh                               K=256, M=768
    mma_gemmh<false, true, false><<<dim3(6, rowBlocks), blk, SM_TOTAL>>>(
        (hfp)hh_f, whh_f, b_hh, gh, nullptr, HD, H3);
    // 4) GRU k=0 gates -> h1 (fp32 + fp16)
    gates0_kernel<<<(NROWS * 64) / 256, 256>>>(gh, b_ih, h, h1, (uint2*)h1_f);
    // 5) S[b] = sum_a h1[b,a]  -> S_f
    commS_kernel<<<NB, HD>>>(h1, (hfpm)S_f);
    // 6) Sg = S @ W_ih^T  (bias = zeros half of bias_cat)     rows=2048, M=768
    mma_gemmh<false, true, false><<<dim3(6, NB / 128), blk, SM_TOTAL>>>(
        (hfp)S_f, (hfp)wcat_f, bias_cat, sg, nullptr, HD, H3);
    // 7) gcat = h1 @ [W_ih; W_hh]^T + [0; b_hh]               M=1536
    mma_gemmh<false, true, false><<<dim3(12, rowBlocks), blk, SM_TOTAL>>>(
        (hfp)h1_f, (hfp)wcat_f, bias_cat, gcat, nullptr, HD, H6);
    // 8) GRU k=1 gates + decoder -> out
    gates1_dec_kernel<<<NROWS / 4, 256>>>(gcat, sg, b_ih, h1, dec_W, dec_b, out);
}

// round 8
// speedup vs baseline: 2.1210x; 1.0810x over previous
#include <cuda_runtime.h>
#include <cuda_fp16.h>
#include <math.h>
#include <stdint.h>

// Problem constants (B=2048, A=32, D=128, H=256)
#define NB    2048
#define NA    32
#define NROWS (NB * NA)   // 65536
#define DIN   128
#define HD    256
#define H3    768
#define H6    1536

// ---------------------------------------------------------------------------
// Scratch (__device__ globals; uint4 arrays guarantee 16B alignment)
// ---------------------------------------------------------------------------
__device__ float g_h  [(size_t)NROWS * HD];
__device__ float g_h1 [(size_t)NROWS * HD];
__device__ float g_sg [(size_t)NB * H3];       // S @ W_ih^T (fp32)
__device__ float g_bias_cat[H6];

// fp16 buffers
__device__ uint4 g_gh_f  [(size_t)NROWS * H3 / 8];   // k=0 gh (fp16)
__device__ uint4 g_gcat_f[(size_t)NROWS * H6 / 8];   // k=1 [Gih | ghh+b_hh] (fp16)
__device__ uint4 g_obs_f [(size_t)NROWS * DIN / 8];
__device__ uint4 g_e_f   [(size_t)NROWS * HD / 8];
__device__ uint4 g_hh_f  [(size_t)NROWS * HD / 8];
__device__ uint4 g_h1_f  [(size_t)NROWS * HD / 8];
__device__ uint4 g_S_f   [(size_t)NB * HD / 8];
__device__ uint4 g_ew_f  [(size_t)HD * DIN / 8];
__device__ uint4 g_fw_f  [(size_t)HD * HD / 8];
__device__ uint4 g_wcat_f[(size_t)H6 * HD / 8];      // [W_ih; W_hh] fp16

__device__ __forceinline__ float sigmoidf_(float x) { return 1.0f / (1.0f + expf(-x)); }

__device__ __forceinline__ uint32_t smem_to_u32(const void* p) {
    uint32_t a;
    asm("{ .reg .u64 t; cvta.to.shared.u64 t, %1; cvt.u32.u64 %0, t; }" : "=r"(a) : "l"(p));
    return a;
}

#define SMEM_SWIZZLE_128B(off) ((off) ^ (((off) >> 3) & 0x70))

// ---------------------------------------------------------------------------
// mma / ldmatrix / cp.async primitives (baseline sm_80+ ISA)
// ---------------------------------------------------------------------------
__device__ __forceinline__ void mma_f16(float* c, uint32_t a0, uint32_t a1, uint32_t a2,
                                        uint32_t a3, uint32_t b0, uint32_t b1) {
    asm volatile(
        "mma.sync.aligned.m16n8k16.row.col.f32.f16.f16.f32 "
        "{%0,%1,%2,%3}, {%4,%5,%6,%7}, {%8,%9}, {%0,%1,%2,%3};"
        : "+f"(c[0]), "+f"(c[1]), "+f"(c[2]), "+f"(c[3])
        : "r"(a0), "r"(a1), "r"(a2), "r"(a3), "r"(b0), "r"(b1));
}
__device__ __forceinline__ void ldm_x4(uint32_t* r, uint32_t addr) {
    asm volatile("ldmatrix.sync.aligned.m8n8.x4.shared.b16 {%0,%1,%2,%3}, [%4];"
                 : "=r"(r[0]), "=r"(r[1]), "=r"(r[2]), "=r"(r[3]) : "r"(addr));
}
__device__ __forceinline__ void ldm_x2(uint32_t* r, uint32_t addr) {
    asm volatile("ldmatrix.sync.aligned.m8n8.x2.shared.b16 {%0,%1}, [%2];"
                 : "=r"(r[0]), "=r"(r[1]) : "r"(addr));
}
__device__ __forceinline__ void cp16(uint32_t dst, const void* src) {
    asm volatile("cp.async.cg.shared.global [%0], [%1], 16;" :: "r"(dst), "l"(src));
}
#define CP_COMMIT()  asm volatile("cp.async.commit_group;")
#define CP_WAIT(n)   asm volatile("cp.async.wait_group %0;" :: "n"(n))

__device__ __forceinline__ uint32_t pack_h2(float a, float b) {
    __half2 h = __floats2half2_rn(a, b);
    return *reinterpret_cast<uint32_t*>(&h);
}
__device__ __forceinline__ float4 h4_to_f4(uint2 u) {
    float2 fa = __half22float2(*reinterpret_cast<__half2*>(&u.x));
    float2 fb = __half22float2(*reinterpret_cast<__half2*>(&u.y));
    return make_float4(fa.x, fa.y, fb.x, fb.y);
}

// ---------------------------------------------------------------------------
// fp32 -> fp16 conversion (obs, large)
// ---------------------------------------------------------------------------
__global__ void convert_h(const float4* __restrict__ src, uint2* __restrict__ dst, int n4)
{
    const int i = blockIdx.x * blockDim.x + threadIdx.x;
    if (i >= n4) return;
    float4 v = src[i];
    uint2 o;
    o.x = pack_h2(v.x, v.y);
    o.y = pack_h2(v.z, v.w);
    dst[i] = o;
}

// All 4 weight tensors in one launch. Segment sizes (in float4 units):
//   enc_W: 8192, fobs_W: 16384, W_ih: 49152, W_hh: 49152  (total 122880)
__global__ void convert_weights(const float4* __restrict__ ew, const float4* __restrict__ fw,
                                const float4* __restrict__ wih, const float4* __restrict__ whh,
                                uint2* __restrict__ ew_f, uint2* __restrict__ fw_f,
                                uint2* __restrict__ wcat_f)
{
    const int gid = blockIdx.x * blockDim.x + threadIdx.x;
    const float4* src;
    uint2* dst;
    int i;
    if (gid < 8192)        { i = gid;          src = ew;  dst = ew_f; }
    else if (gid < 24576)  { i = gid - 8192;   src = fw;  dst = fw_f; }
    else if (gid < 73728)  { i = gid - 24576;  src = wih; dst = wcat_f; }
    else if (gid < 122880) { i = gid - 73728;  src = whh; dst = wcat_f + 49152; }
    else return;
    float4 v = src[i];
    uint2 o;
    o.x = pack_h2(v.x, v.y);
    o.y = pack_h2(v.z, v.w);
    dst[i] = o;
}

__global__ void bias_cat_kernel(const float* __restrict__ b_hh, float* __restrict__ bias_cat)
{
    const int i = blockIdx.x * blockDim.x + threadIdx.x;
    if (i < H6) bias_cat[i] = (i < H3) ? 0.f : b_hh[i - H3];
}

// ---------------------------------------------------------------------------
// fp16 single-pass GEMM, cp.async 3-stage, 2 CTAs/SM:
//   C[N,M] = A[N,K] @ W[M,K]^T + bias  (A, W fp16; fp32 accumulate)
// CTA tile 128x128, KC=64, 3 stages (96KB smem), 8 warps (2m x 4n).
// ---------------------------------------------------------------------------
#define ST_AH 0
#define ST_WH 16384
#define ST_SZ 32768
#define SM_TOTAL (3 * ST_SZ)

template <bool RELU, bool WF32, bool WHALF>
__global__ __launch_bounds__(256, 2)
void mma_gemmh(const __half* __restrict__ Ag, const __half* __restrict__ Wg,
               const float* __restrict__ bias, float* __restrict__ C,
               __half* __restrict__ Ch, int K, int M)
{
    extern __shared__ char smem[];
    const uint32_t sb = smem_to_u32(smem);
    const int tid  = threadIdx.x;
    const int wid  = tid >> 5;
    const int lane = tid & 31;
    const int row0 = blockIdx.y * 128;
    const int col0 = blockIdx.x * 128;
    const int wm0  = (wid >> 2) * 64;
    const int wn0  = (wid & 3) * 32;

    const int a_row = wm0 + (lane & 15);
    const int a_kb  = ((lane >> 4) & 1) * 16;
    const int b_row = wn0 + (lane & 7);
    const int b_kb  = ((lane >> 3) & 1) * 16;

    uint32_t sw[4];
    const __half *pA[4], *pW[4];
#pragma unroll
    for (int it = 0; it < 4; it++) {
        int g = tid + it * 256;
        int r = g >> 3, k0 = (g & 7) * 8;
        sw[it] = SMEM_SWIZZLE_128B((uint32_t)(r * 128 + k0 * 2));
        pA[it] = Ag + (size_t)(row0 + r) * K + k0;
        pW[it] = Wg + (size_t)(col0 + r) * K + k0;
    }

    float acc[4][4][4];
#pragma unroll
    for (int i = 0; i < 4; i++)
#pragma unroll
        for (int j = 0; j < 4; j++)
#pragma unroll
            for (int q = 0; q < 4; q++) acc[i][j][q] = 0.f;

    const int nch = K >> 6;

#pragma unroll
    for (int it = 0; it < 4; it++) {
        cp16(sb + ST_AH + sw[it], pA[it]);
        cp16(sb + ST_WH + sw[it], pW[it]);
    }
    CP_COMMIT();
    if (nch > 1) {
#pragma unroll
        for (int it = 0; it < 4; it++) {
            cp16(sb + ST_SZ + ST_AH + sw[it], pA[it] + 64);
            cp16(sb + ST_SZ + ST_WH + sw[it], pW[it] + 64);
        }
    }
    CP_COMMIT();

    for (int ch = 0; ch < nch; ch++) {
        const uint32_t sbase = sb + (uint32_t)(ch % 3) * ST_SZ;
        if (ch + 2 < nch) {
            const uint32_t nbase = sb + (uint32_t)((ch + 2) % 3) * ST_SZ;
            const int koff = (ch + 2) * 64;
#pragma unroll
            for (int it = 0; it < 4; it++) {
                cp16(nbase + ST_AH + sw[it], pA[it] + koff);
                cp16(nbase + ST_WH + sw[it], pW[it] + koff);
            }
            CP_COMMIT();
            CP_WAIT(2);
        } else if (ch + 1 < nch) {
            CP_WAIT(1);
        } else {
            CP_WAIT(0);
        }
        __syncthreads();

#pragma unroll
        for (int ks = 0; ks < 4; ks++) {
            uint32_t Af[4][4], Bf[4][2];
#pragma unroll
            for (int fm = 0; fm < 4; fm++) {
                uint32_t loc = SMEM_SWIZZLE_128B((uint32_t)((a_row + fm * 16) * 128 + ks * 32 + a_kb));
                ldm_x4(Af[fm], sbase + ST_AH + loc);
            }
#pragma unroll
            for (int fn = 0; fn < 4; fn++) {
                uint32_t loc = SMEM_SWIZZLE_128B((uint32_t)((b_row + fn * 8) * 128 + ks * 32 + b_kb));
                ldm_x2(Bf[fn], sbase + ST_WH + loc);
            }
#pragma unroll
            for (int fm = 0; fm < 4; fm++)
#pragma unroll
                for (int fn = 0; fn < 4; fn++)
                    mma_f16(acc[fm][fn], Af[fm][0], Af[fm][1], Af[fm][2], Af[fm][3],
                            Bf[fn][0], Bf[fn][1]);
        }
        __syncthreads();
    }

    const int gid  = lane >> 2;
    const int tid4 = lane & 3;
#pragma unroll
    for (int fn = 0; fn < 4; fn++) {
        const int col = col0 + wn0 + fn * 8 + 2 * tid4;
        const float b0 = bias[col], b1 = bias[col + 1];
#pragma unroll
        for (int fm = 0; fm < 4; fm++) {
            const int rlo = row0 + wm0 + fm * 16 + gid;
            float2 v0, v1;
            v0.x = acc[fm][fn][0] + b0;  v0.y = acc[fm][fn][1] + b1;
            v1.x = acc[fm][fn][2] + b0;  v1.y = acc[fm][fn][3] + b1;
            if (RELU) {
                v0.x = fmaxf(v0.x, 0.f); v0.y = fmaxf(v0.y, 0.f);
                v1.x = fmaxf(v1.x, 0.f); v1.y = fmaxf(v1.y, 0.f);
            }
            if (WF32) {
                *reinterpret_cast<float2*>(C + (size_t)rlo * M + col)       = v0;
                *reinterpret_cast<float2*>(C + (size_t)(rlo + 8) * M + col) = v1;
            }
            if (WHALF) {
                *reinterpret_cast<uint32_t*>(Ch + (size_t)rlo * M + col)       = pack_h2(v0.x, v0.y);
                *reinterpret_cast<uint32_t*>(Ch + (size_t)(rlo + 8) * M + col) = pack_h2(v1.x, v1.y);
            }
        }
    }
}

// ---------------------------------------------------------------------------
// GRU gates k=0 fused with per-batch agent sum.
// One block per batch; thread j owns column j across all 32 agents.
//   h1 = (1-z)n + z*h ; S[b,j] = sum_a h1[b,a,j]
// ---------------------------------------------------------------------------
__global__ void gates0S_kernel(const __half* __restrict__ gh,
                               const float* __restrict__ b_ih,
                               const float* __restrict__ h,
                               float* __restrict__ h1,
                               __half* __restrict__ h1_f,
                               __half* __restrict__ S_f)
{
    const int b = blockIdx.x;
    const int j = threadIdx.x;
    const __half* ghb = gh + (size_t)b * NA * H3;
    const float*  hb  = h  + (size_t)b * NA * HD;
    float* h1b        = h1   + (size_t)b * NA * HD;
    __half* h1fb      = h1_f + (size_t)b * NA * HD;
    const float bir = b_ih[j], biz = b_ih[HD + j], bin = b_ih[2 * HD + j];
    float s = 0.f;
    for (int a = 0; a < NA; a++) {
        float gr = __half2float(ghb[a * H3 + j]);
        float gz = __half2float(ghb[a * H3 + HD + j]);
        float gn = __half2float(ghb[a * H3 + 2 * HD + j]);
        float hh = hb[a * HD + j];
        float r = sigmoidf_(bir + gr), z = sigmoidf_(biz + gz);
        float n = tanhf(bin + r * gn);
        float o = (1.f - z) * n + z * hh;
        h1b[a * HD + j]  = o;
        h1fb[a * HD + j] = __float2half_rn(o);
        s += o;
    }
    S_f[(size_t)b * HD + j] = __float2half_rn(s);
}

// ---------------------------------------------------------------------------
// GRU gates k=1 + decoder.  gi = (Sg[b] - Gih[i]) / NA + b_ih.
// gcat (fp16) row layout: [Gih (768) | ghh (768, includes b_hh)]
// ---------------------------------------------------------------------------
__global__ void gates1_dec_kernel(const __half* __restrict__ gcat,
                                  const float* __restrict__ Sg,
                                  const float* __restrict__ b_ih,
                                  const float* __restrict__ h1,
                                  const float* __restrict__ dec_W,
                                  const float* __restrict__ dec_b,
                                  float* __restrict__ out)
{
    const int tid = threadIdx.x;
    const int i = blockIdx.x * 4 + (tid >> 6);
    const int b = i >> 5;              // batch index (NA = 32)
    const int q = tid & 63;
    const uint2*  gc = reinterpret_cast<const uint2*>(gcat + (size_t)i * H6);   // 4 halves each
    const float4* sg = reinterpret_cast<const float4*>(Sg + (size_t)b * H3);
    const float4* bi = reinterpret_cast<const float4*>(b_ih);
    const float inv = 1.f / (float)NA;

    float4 gih_r = h4_to_f4(gc[q]);
    float4 gih_z = h4_to_f4(gc[64 + q]);
    float4 gih_n = h4_to_f4(gc[128 + q]);
    float4 hr    = h4_to_f4(gc[192 + q]);
    float4 hz    = h4_to_f4(gc[256 + q]);
    float4 hn    = h4_to_f4(gc[320 + q]);
    float4 sg_r = sg[q],  sg_z = sg[64 + q],  sg_n = sg[128 + q];
    float4 bi_r = bi[q],  bi_z = bi[64 + q],  bi_n = bi[128 + q];
    float4 ir, iz, in_;
    ir.x = (sg_r.x - gih_r.x) * inv + bi_r.x;  ir.y = (sg_r.y - gih_r.y) * inv + bi_r.y;
    ir.z = (sg_r.z - gih_r.z) * inv + bi_r.z;  ir.w = (sg_r.w - gih_r.w) * inv + bi_r.w;
    iz.x = (sg_z.x - gih_z.x) * inv + bi_z.x;  iz.y = (sg_z.y - gih_z.y) * inv + bi_z.y;
    iz.z = (sg_z.z - gih_z.z) * inv + bi_z.z;  iz.w = (sg_z.w - gih_z.w) * inv + bi_z.w;
    in_.x = (sg_n.x - gih_n.x) * inv + bi_n.x; in_.y = (sg_n.y - gih_n.y) * inv + bi_n.y;
    in_.z = (sg_n.z - gih_n.z) * inv + bi_n.z; in_.w = (sg_n.w - gih_n.w) * inv + bi_n.w;

    float4 hp = reinterpret_cast<const float4*>(h1)[(size_t)i * 64 + q];
    float4 dw = reinterpret_cast<const float4*>(dec_W)[q];

    float p = 0.f;
    { float r = sigmoidf_(ir.x + hr.x), z = sigmoidf_(iz.x + hz.x);
      float n = tanhf(in_.x + r * hn.x); p += ((1.f - z) * n + z * hp.x) * dw.x; }
    { float r = sigmoidf_(ir.y + hr.y), z = sigmoidf_(iz.y + hz.y);
      float n = tanhf(in_.y + r * hn.y); p += ((1.f - z) * n + z * hp.y) * dw.y; }
    { float r = sigmoidf_(ir.z + hr.z), z = sigmoidf_(iz.z + hz.z);
      float n = tanhf(in_.z + r * hn.z); p += ((1.f - z) * n + z * hp.z) * dw.z; }
    { float r = sigmoidf_(ir.w + hr.w), z = sigmoidf_(iz.w + hz.w);
      float n = tanhf(in_.w + r * hn.w); p += ((1.f - z) * n + z * hp.w) * dw.w; }
#pragma unroll
    for (int o = 16; o > 0; o >>= 1) p += __shfl_down_sync(0xffffffffu, p, o);
    __shared__ float red[8];
    if ((tid & 31) == 0) red[tid >> 5] = p;
    __syncthreads();
    if (tid < 4) out[blockIdx.x * 4 + tid] = red[2 * tid] + red[2 * tid + 1] + dec_b[0];
}

// ---------------------------------------------------------------------------
// Launch
// ---------------------------------------------------------------------------
extern "C" void kernel_launch(void* const* d_in, const int* in_sizes, int n_in,
                              void* d_out, int out_size)
{
    const float* obs    = (const float*)d_in[0];
    const float* enc_W  = (const float*)d_in[2];
    const float* enc_b  = (const float*)d_in[3];
    const float* fobs_W = (const float*)d_in[4];
    const float* fobs_b = (const float*)d_in[5];
    const float* W_ih   = (const float*)d_in[6];
    const float* b_ih   = (const float*)d_in[7];
    const float* W_hh   = (const float*)d_in[8];
    const float* b_hh   = (const float*)d_in[9];
    const float* dec_W  = (const float*)d_in[10];
    const float* dec_b  = (const float*)d_in[11];
    float* out = (float*)d_out;

    float *h, *h1, *sg, *bias_cat;
    cudaGetSymbolAddress((void**)&h,    g_h);
    cudaGetSymbolAddress((void**)&h1,   g_h1);
    cudaGetSymbolAddress((void**)&sg,   g_sg);
    cudaGetSymbolAddress((void**)&bias_cat, g_bias_cat);

    void *gh_f, *gcat_f, *obs_f, *e_f, *hh_f, *h1_f, *S_f, *ew_f, *fw_f, *wcat_f;
    cudaGetSymbolAddress(&gh_f,   g_gh_f);
    cudaGetSymbolAddress(&gcat_f, g_gcat_f);
    cudaGetSymbolAddress(&obs_f,  g_obs_f);
    cudaGetSymbolAddress(&e_f,    g_e_f);
    cudaGetSymbolAddress(&hh_f,   g_hh_f);
    cudaGetSymbolAddress(&h1_f,   g_h1_f);
    cudaGetSymbolAddress(&S_f,    g_S_f);
    cudaGetSymbolAddress(&ew_f,   g_ew_f);
    cudaGetSymbolAddress(&fw_f,   g_fw_f);
    cudaGetSymbolAddress(&wcat_f, g_wcat_f);

    cudaFuncSetAttribute(mma_gemmh<true , false, true >, cudaFuncAttributeMaxDynamicSharedMemorySize, SM_TOTAL);
    cudaFuncSetAttribute(mma_gemmh<false, true , true >, cudaFuncAttributeMaxDynamicSharedMemorySize, SM_TOTAL);
    cudaFuncSetAttribute(mma_gemmh<false, false, true >, cudaFuncAttributeMaxDynamicSharedMemorySize, SM_TOTAL);
    cudaFuncSetAttribute(mma_gemmh<false, true , false>, cudaFuncAttributeMaxDynamicSharedMemorySize, SM_TOTAL);

    typedef const __half* hfp;
    typedef __half* hfpm;

    // 0) convert obs (big) + all weights (one kernel) + bias_cat
    convert_h<<<(NROWS * DIN / 4 + 255) / 256, 256>>>((const float4*)obs, (uint2*)obs_f, NROWS * DIN / 4);
    convert_weights<<<480, 256>>>((const float4*)enc_W, (const float4*)fobs_W,
                                  (const float4*)W_ih, (const float4*)W_hh,
                                  (uint2*)ew_f, (uint2*)fw_f, (uint2*)wcat_f);
    bias_cat_kernel<<<(H6 + 255) / 256, 256>>>(b_hh, bias_cat);

    const dim3 blk(256);
    const int rowBlocks = NROWS / 128;  // 512
    const __half* whh_f = (hfp)wcat_f + (size_t)H3 * HD;

    // 1) e = relu(obs @ enc_W^T + enc_b) -> e_f              K=128, M=256
    mma_gemmh<true, false, true><<<dim3(2, rowBlocks), blk, SM_TOTAL>>>(
        (hfp)obs_f, (hfp)ew_f, enc_b, nullptr, (hfpm)e_f, DIN, HD);
    // 2) h = e @ fobs_W^T + fobs_b -> h fp32 + hh_f           K=256, M=256
    mma_gemmh<false, true, true><<<dim3(2, rowBlocks), blk, SM_TOTAL>>>(
        (hfp)e_f, (hfp)fw_f, fobs_b, h, (hfpm)hh_f, HD, HD);
    // 3) gh = h @ W_hh^T + b_hh  -> fp16                      K=256, M=768
    mma_gemmh<false, false, true><<<dim3(6, rowBlocks), blk, SM_TOTAL>>>(
        (hfp)hh_f, whh_f, b_hh, nullptr, (hfpm)gh_f, HD, H3);
    // 4) GRU k=0 gates + agent sum -> h1 (fp32+fp16), S_f
    gates0S_kernel<<<NB, HD>>>((hfp)gh_f, b_ih, h, h1, (hfpm)h1_f, (hfpm)S_f);
    // 5) Sg = S @ W_ih^T (fp32; bias = zeros half of bias_cat)  rows=2048, M=768
    mma_gemmh<false, true, false><<<dim3(6, NB / 128), blk, SM_TOTAL>>>(
        (hfp)S_f, (hfp)wcat_f, bias_cat, sg, nullptr, HD, H3);
    // 6) gcat = h1 @ [W_ih; W_hh]^T + [0; b_hh] -> fp16       M=1536
    mma_gemmh<false, false, true><<<dim3(12, rowBlocks), blk, SM_TOTAL>>>(
        (hfp)h1_f, (hfp)wcat_f, bias_cat, nullptr, (hfpm)gcat_f, HD, H6);
    // 7) GRU k=1 gates + decoder -> out
    gates1_dec_kernel<<<NROWS / 4, 256>>>((hfp)gcat_f, sg, b_ih, h1, dec_W, dec_b, out);
}

// round 9
// speedup vs baseline: 2.2567x; 1.0639x over previous
#include <cuda_runtime.h>
#include <cuda_fp16.h>
#include <math.h>
#include <stdint.h>

// Problem constants (B=2048, A=32, D=128, H=256)
#define NB    2048
#define NA    32
#define NROWS (NB * NA)   // 65536
#define DIN   128
#define HD    256
#define H3    768
#define H6    1536

// ---------------------------------------------------------------------------
// Scratch
// ---------------------------------------------------------------------------
__device__ float g_h  [(size_t)NROWS * HD];
__device__ float g_h1 [(size_t)NROWS * HD];
__device__ float g_sg [(size_t)NB * H3];
__device__ float g_bias_cat[H6];

__device__ uint4 g_gh_f  [(size_t)NROWS * H3 / 8];
__device__ uint4 g_gcat_f[(size_t)NROWS * H6 / 8];
__device__ uint4 g_obs_f [(size_t)NROWS * DIN / 8];
__device__ uint4 g_e_f   [(size_t)NROWS * HD / 8];
__device__ uint4 g_hh_f  [(size_t)NROWS * HD / 8];
__device__ uint4 g_h1_f  [(size_t)NROWS * HD / 8];
__device__ uint4 g_S_f   [(size_t)NB * HD / 8];
__device__ uint4 g_ew_f  [(size_t)HD * DIN / 8];
__device__ uint4 g_fw_f  [(size_t)HD * HD / 8];
__device__ uint4 g_wcat_f[(size_t)H6 * HD / 8];

__device__ __forceinline__ float sigmoidf_(float x) { return 1.0f / (1.0f + expf(-x)); }

__device__ __forceinline__ uint32_t smem_to_u32(const void* p) {
    uint32_t a;
    asm("{ .reg .u64 t; cvta.to.shared.u64 t, %1; cvt.u32.u64 %0, t; }" : "=r"(a) : "l"(p));
    return a;
}

#define SMEM_SWIZZLE_128B(off) ((off) ^ (((off) >> 3) & 0x70))

// ---------------------------------------------------------------------------
// primitives
// ---------------------------------------------------------------------------
__device__ __forceinline__ void mma_f16(float* c, uint32_t a0, uint32_t a1, uint32_t a2,
                                        uint32_t a3, uint32_t b0, uint32_t b1) {
    asm volatile(
        "mma.sync.aligned.m16n8k16.row.col.f32.f16.f16.f32 "
        "{%0,%1,%2,%3}, {%4,%5,%6,%7}, {%8,%9}, {%0,%1,%2,%3};"
        : "+f"(c[0]), "+f"(c[1]), "+f"(c[2]), "+f"(c[3])
        : "r"(a0), "r"(a1), "r"(a2), "r"(a3), "r"(b0), "r"(b1));
}
__device__ __forceinline__ void ldm_x4(uint32_t* r, uint32_t addr) {
    asm volatile("ldmatrix.sync.aligned.m8n8.x4.shared.b16 {%0,%1,%2,%3}, [%4];"
                 : "=r"(r[0]), "=r"(r[1]), "=r"(r[2]), "=r"(r[3]) : "r"(addr));
}
__device__ __forceinline__ void ldm_x2(uint32_t* r, uint32_t addr) {
    asm volatile("ldmatrix.sync.aligned.m8n8.x2.shared.b16 {%0,%1}, [%2];"
                 : "=r"(r[0]), "=r"(r[1]) : "r"(addr));
}
__device__ __forceinline__ void cp16(uint32_t dst, const void* src) {
    asm volatile("cp.async.cg.shared.global [%0], [%1], 16;" :: "r"(dst), "l"(src));
}
#define CP_COMMIT()  asm volatile("cp.async.commit_group;")
#define CP_WAIT(n)   asm volatile("cp.async.wait_group %0;" :: "n"(n))

__device__ __forceinline__ uint32_t pack_h2(float a, float b) {
    __half2 h = __floats2half2_rn(a, b);
    return *reinterpret_cast<uint32_t*>(&h);
}
__device__ __forceinline__ float4 h4_to_f4(uint2 u) {
    float2 fa = __half22float2(*reinterpret_cast<__half2*>(&u.x));
    float2 fb = __half22float2(*reinterpret_cast<__half2*>(&u.y));
    return make_float4(fa.x, fa.y, fb.x, fb.y);
}

// ---------------------------------------------------------------------------
// conversions
// ---------------------------------------------------------------------------
__global__ void convert_h(const float4* __restrict__ src, uint2* __restrict__ dst, int n4)
{
    const int i = blockIdx.x * blockDim.x + threadIdx.x;
    if (i >= n4) return;
    float4 v = src[i];
    uint2 o;
    o.x = pack_h2(v.x, v.y);
    o.y = pack_h2(v.z, v.w);
    dst[i] = o;
}

__global__ void convert_weights(const float4* __restrict__ ew, const float4* __restrict__ fw,
                                const float4* __restrict__ wih, const float4* __restrict__ whh,
                                uint2* __restrict__ ew_f, uint2* __restrict__ fw_f,
                                uint2* __restrict__ wcat_f)
{
    const int gid = blockIdx.x * blockDim.x + threadIdx.x;
    const float4* src;
    uint2* dst;
    int i;
    if (gid < 8192)        { i = gid;          src = ew;  dst = ew_f; }
    else if (gid < 24576)  { i = gid - 8192;   src = fw;  dst = fw_f; }
    else if (gid < 73728)  { i = gid - 24576;  src = wih; dst = wcat_f; }
    else if (gid < 122880) { i = gid - 73728;  src = whh; dst = wcat_f + 49152; }
    else return;
    float4 v = src[i];
    uint2 o;
    o.x = pack_h2(v.x, v.y);
    o.y = pack_h2(v.z, v.w);
    dst[i] = o;
}

__global__ void bias_cat_kernel(const float* __restrict__ b_hh, float* __restrict__ bias_cat)
{
    const int i = blockIdx.x * blockDim.x + threadIdx.x;
    if (i < H6) bias_cat[i] = (i < H3) ? 0.f : b_hh[i - H3];
}

// ---------------------------------------------------------------------------
// fp16 GEMM, cp.async 3-stage, 1 sync/chunk, ks-level fragment double-buffer.
// CTA tile 128x128, KC=64, 8 warps (2m x 4n), 2 CTAs/SM.
// ---------------------------------------------------------------------------
#define ST_AH 0
#define ST_WH 16384
#define ST_SZ 32768
#define SM_TOTAL (3 * ST_SZ)

template <bool RELU, bool WF32, bool WHALF>
__global__ __launch_bounds__(256, 2)
void mma_gemmh(const __half* __restrict__ Ag, const __half* __restrict__ Wg,
               const float* __restrict__ bias, float* __restrict__ C,
               __half* __restrict__ Ch, int K, int M)
{
    extern __shared__ char smem[];
    const uint32_t sb = smem_to_u32(smem);
    const int tid  = threadIdx.x;
    const int wid  = tid >> 5;
    const int lane = tid & 31;
    const int row0 = blockIdx.y * 128;
    const int col0 = blockIdx.x * 128;
    const int wm0  = (wid >> 2) * 64;
    const int wn0  = (wid & 3) * 32;

    const int a_row = wm0 + (lane & 15);
    const int a_kb  = ((lane >> 4) & 1) * 16;
    const int b_row = wn0 + (lane & 7);
    const int b_kb  = ((lane >> 3) & 1) * 16;

    // tile-load mapping, collapsed to bases (it-th chunk: +it*32*K, smem +it*4096;
    // swizzle only touches bits [9:7], so +4096 strides commute with it)
    const int g0 = tid;
    const int r0_ = g0 >> 3, k00 = (g0 & 7) * 8;
    const uint32_t sw0 = SMEM_SWIZZLE_128B((uint32_t)(r0_ * 128 + k00 * 2));
    const __half* pA0 = Ag + (size_t)(row0 + r0_) * K + k00;
    const __half* pW0 = Wg + (size_t)(col0 + r0_) * K + k00;
    const size_t itK = (size_t)32 * K;

    float acc[4][4][4];
#pragma unroll
    for (int i = 0; i < 4; i++)
#pragma unroll
        for (int j = 0; j < 4; j++)
#pragma unroll
            for (int q = 0; q < 4; q++) acc[i][j][q] = 0.f;

    const int nch = K >> 6;

    // prologue: prefetch chunks 0 and 1
#pragma unroll
    for (int it = 0; it < 4; it++) {
        cp16(sb + ST_AH + sw0 + it * 4096, pA0 + it * itK);
        cp16(sb + ST_WH + sw0 + it * 4096, pW0 + it * itK);
    }
    CP_COMMIT();
    if (nch > 1) {
#pragma unroll
        for (int it = 0; it < 4; it++) {
            cp16(sb + ST_SZ + ST_AH + sw0 + it * 4096, pA0 + it * itK + 64);
            cp16(sb + ST_SZ + ST_WH + sw0 + it * 4096, pW0 + it * itK + 64);
        }
    }
    CP_COMMIT();

    // per-warp ldmatrix base offsets (pre-swizzled components)
    uint32_t Af[2][4][4], Bf[2][4][2];

    for (int ch = 0; ch < nch; ch++) {
        const uint32_t sbase = sb + (uint32_t)(ch % 3) * ST_SZ;
        if (ch + 1 < nch) { CP_WAIT(1); } else { CP_WAIT(0); }
        __syncthreads();
        // prefetch chunk ch+2 into stage (ch+2)%3 (safe: all warps past compute ch-1)
        if (ch + 2 < nch) {
            const uint32_t nbase = sb + (uint32_t)((ch + 2) % 3) * ST_SZ;
            const int koff = (ch + 2) * 64;
#pragma unroll
            for (int it = 0; it < 4; it++) {
                cp16(nbase + ST_AH + sw0 + it * 4096, pA0 + it * itK + koff);
                cp16(nbase + ST_WH + sw0 + it * 4096, pW0 + it * itK + koff);
            }
            CP_COMMIT();
        } else {
            CP_COMMIT();  // keep group numbering uniform
        }

        // preload fragments for ks=0
#pragma unroll
        for (int fm = 0; fm < 4; fm++) {
            uint32_t loc = SMEM_SWIZZLE_128B((uint32_t)((a_row + fm * 16) * 128 + a_kb));
            ldm_x4(Af[0][fm], sbase + ST_AH + loc);
        }
#pragma unroll
        for (int fn = 0; fn < 4; fn++) {
            uint32_t loc = SMEM_SWIZZLE_128B((uint32_t)((b_row + fn * 8) * 128 + b_kb));
            ldm_x2(Bf[0][fn], sbase + ST_WH + loc);
        }

#pragma unroll
        for (int ks = 0; ks < 4; ks++) {
            const int cur = ks & 1, nxt = cur ^ 1;
            if (ks < 3) {
#pragma unroll
                for (int fm = 0; fm < 4; fm++) {
                    uint32_t loc = SMEM_SWIZZLE_128B(
                        (uint32_t)((a_row + fm * 16) * 128 + (ks + 1) * 32 + a_kb));
                    ldm_x4(Af[nxt][fm], sbase + ST_AH + loc);
                }
#pragma unroll
                for (int fn = 0; fn < 4; fn++) {
                    uint32_t loc = SMEM_SWIZZLE_128B(
                        (uint32_t)((b_row + fn * 8) * 128 + (ks + 1) * 32 + b_kb));
                    ldm_x2(Bf[nxt][fn], sbase + ST_WH + loc);
                }
            }
#pragma unroll
            for (int fm = 0; fm < 4; fm++)
#pragma unroll
                for (int fn = 0; fn < 4; fn++)
                    mma_f16(acc[fm][fn], Af[cur][fm][0], Af[cur][fm][1], Af[cur][fm][2],
                            Af[cur][fm][3], Bf[cur][fn][0], Bf[cur][fn][1]);
        }
        // no trailing sync: next iteration's top sync protects stage reuse
    }

    const int gid  = lane >> 2;
    const int tid4 = lane & 3;
#pragma unroll
    for (int fn = 0; fn < 4; fn++) {
        const int col = col0 + wn0 + fn * 8 + 2 * tid4;
        const float b0 = bias[col], b1 = bias[col + 1];
#pragma unroll
        for (int fm = 0; fm < 4; fm++) {
            const int rlo = row0 + wm0 + fm * 16 + gid;
            float2 v0, v1;
            v0.x = acc[fm][fn][0] + b0;  v0.y = acc[fm][fn][1] + b1;
            v1.x = acc[fm][fn][2] + b0;  v1.y = acc[fm][fn][3] + b1;
            if (RELU) {
                v0.x = fmaxf(v0.x, 0.f); v0.y = fmaxf(v0.y, 0.f);
                v1.x = fmaxf(v1.x, 0.f); v1.y = fmaxf(v1.y, 0.f);
            }
            if (WF32) {
                *reinterpret_cast<float2*>(C + (size_t)rlo * M + col)       = v0;
                *reinterpret_cast<float2*>(C + (size_t)(rlo + 8) * M + col) = v1;
            }
            if (WHALF) {
                *reinterpret_cast<uint32_t*>(Ch + (size_t)rlo * M + col)       = pack_h2(v0.x, v0.y);
                *reinterpret_cast<uint32_t*>(Ch + (size_t)(rlo + 8) * M + col) = pack_h2(v1.x, v1.y);
            }
        }
    }
}

// ---------------------------------------------------------------------------
// GRU gates k=0 fused with per-batch agent sum.
// ---------------------------------------------------------------------------
__global__ void gates0S_kernel(const __half* __restrict__ gh,
                               const float* __restrict__ b_ih,
                               const float* __restrict__ h,
                               float* __restrict__ h1,
                               __half* __restrict__ h1_f,
                               __half* __restrict__ S_f)
{
    const int b = blockIdx.x;
    const int j = threadIdx.x;
    const __half* ghb = gh + (size_t)b * NA * H3;
    const float*  hb  = h  + (size_t)b * NA * HD;
    float* h1b        = h1   + (size_t)b * NA * HD;
    __half* h1fb      = h1_f + (size_t)b * NA * HD;
    const float bir = b_ih[j], biz = b_ih[HD + j], bin = b_ih[2 * HD + j];
    float s = 0.f;
    for (int a = 0; a < NA; a++) {
        float gr = __half2float(ghb[a * H3 + j]);
        float gz = __half2float(ghb[a * H3 + HD + j]);
        float gn = __half2float(ghb[a * H3 + 2 * HD + j]);
        float hh = hb[a * HD + j];
        float r = sigmoidf_(bir + gr), z = sigmoidf_(biz + gz);
        float n = tanhf(bin + r * gn);
        float o = (1.f - z) * n + z * hh;
        h1b[a * HD + j]  = o;
        h1fb[a * HD + j] = __float2half_rn(o);
        s += o;
    }
    S_f[(size_t)b * HD + j] = __float2half_rn(s);
}

// ---------------------------------------------------------------------------
// GRU gates k=1 + decoder.
// ---------------------------------------------------------------------------
__global__ void gates1_dec_kernel(const __half* __restrict__ gcat,
                                  const float* __restrict__ Sg,
                                  const float* __restrict__ b_ih,
                                  const float* __restrict__ h1,
                                  const float* __restrict__ dec_W,
                                  const float* __restrict__ dec_b,
                                  float* __restrict__ out)
{
    const int tid = threadIdx.x;
    const int i = blockIdx.x * 4 + (tid >> 6);
    const int b = i >> 5;
    const int q = tid & 63;
    const uint2*  gc = reinterpret_cast<const uint2*>(gcat + (size_t)i * H6);
    const float4* sg = reinterpret_cast<const float4*>(Sg + (size_t)b * H3);
    const float4* bi = reinterpret_cast<const float4*>(b_ih);
    const float inv = 1.f / (float)NA;

    float4 gih_r = h4_to_f4(gc[q]);
    float4 gih_z = h4_to_f4(gc[64 + q]);
    float4 gih_n = h4_to_f4(gc[128 + q]);
    float4 hr    = h4_to_f4(gc[192 + q]);
    float4 hz    = h4_to_f4(gc[256 + q]);
    float4 hn    = h4_to_f4(gc[320 + q]);
    float4 sg_r = sg[q],  sg_z = sg[64 + q],  sg_n = sg[128 + q];
    float4 bi_r = bi[q],  bi_z = bi[64 + q],  bi_n = bi[128 + q];
    float4 ir, iz, in_;
    ir.x = (sg_r.x - gih_r.x) * inv + bi_r.x;  ir.y = (sg_r.y - gih_r.y) * inv + bi_r.y;
    ir.z = (sg_r.z - gih_r.z) * inv + bi_r.z;  ir.w = (sg_r.w - gih_r.w) * inv + bi_r.w;
    iz.x = (sg_z.x - gih_z.x) * inv + bi_z.x;  iz.y = (sg_z.y - gih_z.y) * inv + bi_z.y;
    iz.z = (sg_z.z - gih_z.z) * inv + bi_z.z;  iz.w = (sg_z.w - gih_z.w) * inv + bi_z.w;
    in_.x = (sg_n.x - gih_n.x) * inv + bi_n.x; in_.y = (sg_n.y - gih_n.y) * inv + bi_n.y;
    in_.z = (sg_n.z - gih_n.z) * inv + bi_n.z; in_.w = (sg_n.w - gih_n.w) * inv + bi_n.w;

    float4 hp = reinterpret_cast<const float4*>(h1)[(size_t)i * 64 + q];
    float4 dw = reinterpret_cast<const float4*>(dec_W)[q];

    float p = 0.f;
    { float r = sigmoidf_(ir.x + hr.x), z = sigmoidf_(iz.x + hz.x);
      float n = tanhf(in_.x + r * hn.x); p += ((1.f - z) * n + z * hp.x) * dw.x; }
    { float r = sigmoidf_(ir.y + hr.y), z = sigmoidf_(iz.y + hz.y);
      float n = tanhf(in_.y + r * hn.y); p += ((1.f - z) * n + z * hp.y) * dw.y; }
    { float r = sigmoidf_(ir.z + hr.z), z = sigmoidf_(iz.z + hz.z);
      float n = tanhf(in_.z + r * hn.z); p += ((1.f - z) * n + z * hp.z) * dw.z; }
    { float r = sigmoidf_(ir.w + hr.w), z = sigmoidf_(iz.w + hz.w);
      float n = tanhf(in_.w + r * hn.w); p += ((1.f - z) * n + z * hp.w) * dw.w; }
#pragma unroll
    for (int o = 16; o > 0; o >>= 1) p += __shfl_down_sync(0xffffffffu, p, o);
    __shared__ float red[8];
    if ((tid & 31) == 0) red[tid >> 5] = p;
    __syncthreads();
    if (tid < 4) out[blockIdx.x * 4 + tid] = red[2 * tid] + red[2 * tid + 1] + dec_b[0];
}

// ---------------------------------------------------------------------------
// Launch
// ---------------------------------------------------------------------------
extern "C" void kernel_launch(void* const* d_in, const int* in_sizes, int n_in,
                              void* d_out, int out_size)
{
    const float* obs    = (const float*)d_in[0];
    const float* enc_W  = (const float*)d_in[2];
    const float* enc_b  = (const float*)d_in[3];
    const float* fobs_W = (const float*)d_in[4];
    const float* fobs_b = (const float*)d_in[5];
    const float* W_ih   = (const float*)d_in[6];
    const float* b_ih   = (const float*)d_in[7];
    const float* W_hh   = (const float*)d_in[8];
    const float* b_hh   = (const float*)d_in[9];
    const float* dec_W  = (const float*)d_in[10];
    const float* dec_b  = (const float*)d_in[11];
    float* out = (float*)d_out;

    float *h, *h1, *sg, *bias_cat;
    cudaGetSymbolAddress((void**)&h,    g_h);
    cudaGetSymbolAddress((void**)&h1,   g_h1);
    cudaGetSymbolAddress((void**)&sg,   g_sg);
    cudaGetSymbolAddress((void**)&bias_cat, g_bias_cat);

    void *gh_f, *gcat_f, *obs_f, *e_f, *hh_f, *h1_f, *S_f, *ew_f, *fw_f, *wcat_f;
    cudaGetSymbolAddress(&gh_f,   g_gh_f);
    cudaGetSymbolAddress(&gcat_f, g_gcat_f);
    cudaGetSymbolAddress(&obs_f,  g_obs_f);
    cudaGetSymbolAddress(&e_f,    g_e_f);
    cudaGetSymbolAddress(&hh_f,   g_hh_f);
    cudaGetSymbolAddress(&h1_f,   g_h1_f);
    cudaGetSymbolAddress(&S_f,    g_S_f);
    cudaGetSymbolAddress(&ew_f,   g_ew_f);
    cudaGetSymbolAddress(&fw_f,   g_fw_f);
    cudaGetSymbolAddress(&wcat_f, g_wcat_f);

    cudaFuncSetAttribute(mma_gemmh<true , false, true >, cudaFuncAttributeMaxDynamicSharedMemorySize, SM_TOTAL);
    cudaFuncSetAttribute(mma_gemmh<false, true , true >, cudaFuncAttributeMaxDynamicSharedMemorySize, SM_TOTAL);
    cudaFuncSetAttribute(mma_gemmh<false, false, true >, cudaFuncAttributeMaxDynamicSharedMemorySize, SM_TOTAL);
    cudaFuncSetAttribute(mma_gemmh<false, true , false>, cudaFuncAttributeMaxDynamicSharedMemorySize, SM_TOTAL);

    typedef const __half* hfp;
    typedef __half* hfpm;

    convert_h<<<(NROWS * DIN / 4 + 255) / 256, 256>>>((const float4*)obs, (uint2*)obs_f, NROWS * DIN / 4);
    convert_weights<<<480, 256>>>((const float4*)enc_W, (const float4*)fobs_W,
                                  (const float4*)W_ih, (const float4*)W_hh,
                                  (uint2*)ew_f, (uint2*)fw_f, (uint2*)wcat_f);
    bias_cat_kernel<<<(H6 + 255) / 256, 256>>>(b_hh, bias_cat);

    const dim3 blk(256);
    const int rowBlocks = NROWS / 128;  // 512
    const __half* whh_f = (hfp)wcat_f + (size_t)H3 * HD;

    // 1) e = relu(obs @ enc_W^T + enc_b)
    mma_gemmh<true, false, true><<<dim3(2, rowBlocks), blk, SM_TOTAL>>>(
        (hfp)obs_f, (hfp)ew_f, enc_b, nullptr, (hfpm)e_f, DIN, HD);
    // 2) h = e @ fobs_W^T + fobs_b
    mma_gemmh<false, true, true><<<dim3(2, rowBlocks), blk, SM_TOTAL>>>(
        (hfp)e_f, (hfp)fw_f, fobs_b, h, (hfpm)hh_f, HD, HD);
    // 3) gh = h @ W_hh^T + b_hh  -> fp16
    mma_gemmh<false, false, true><<<dim3(6, rowBlocks), blk, SM_TOTAL>>>(
        (hfp)hh_f, whh_f, b_hh, nullptr, (hfpm)gh_f, HD, H3);
    // 4) gates k=0 + agent sum
    gates0S_kernel<<<NB, HD>>>((hfp)gh_f, b_ih, h, h1, (hfpm)h1_f, (hfpm)S_f);
    // 5) Sg = S @ W_ih^T
    mma_gemmh<false, true, false><<<dim3(6, NB / 128), blk, SM_TOTAL>>>(
        (hfp)S_f, (hfp)wcat_f, bias_cat, sg, nullptr, HD, H3);
    // 6) gcat = h1 @ [W_ih; W_hh]^T + [0; b_hh] -> fp16
    mma_gemmh<false, false, true><<<dim3(12, rowBlocks), blk, SM_TOTAL>>>(
        (hfp)h1_f, (hfp)wcat_f, bias_cat, nullptr, (hfpm)gcat_f, HD, H6);
    // 7) gates k=1 + decoder
    gates1_dec_kernel<<<NROWS / 4, 256>>>((hfp)gcat_f, sg, b_ih, h1, dec_W, dec_b, out);
}